// round 14
// baseline (speedup 1.0000x reference)
#include <cuda_runtime.h>
#include <cuda_fp16.h>
#include <cstdint>

#define Hdim 128
#define Odim 32
#define INdim 64
#define RB 8
#define NTHR 128
#define MAXB 16384
#define MAXLVL 6

__device__ float g_H0 [(size_t)MAXB * Hdim];
__device__ float g_HAI[(size_t)MAXLVL * MAXB * Hdim];
__device__ float g_H2 [(size_t)MAXLVL * MAXB * Hdim];
__device__ float g_PR [(size_t)(MAXLVL + 1) * MAXB * Odim];

__device__ float g_WPRED[4096];
__device__ __align__(1024) unsigned char g_WTC [163840]; // gru_a  [5][512n][64B]
__device__ __align__(1024) unsigned char g_WTCF[163840]; // gru_f  [5][512n][64B]
__device__ __align__(1024) unsigned char g_WU  [65536];  // uf;ua  [8][128n][64B]

typedef unsigned long long u64;

__device__ __forceinline__ void ffma2(u64& d, u64 a, u64 b) {
    asm volatile("fma.rn.f32x2 %0, %1, %2, %0;" : "+l"(d) : "l"(a), "l"(b));
}
__device__ __forceinline__ u64 pack2(float lo, float hi) {
    u64 r; asm("mov.b64 %0, {%1, %2};" : "=l"(r) : "f"(lo), "f"(hi)); return r;
}
__device__ __forceinline__ float f2sum(u64 v) {
    float lo, hi; asm("mov.b64 {%0, %1}, %2;" : "=f"(lo), "=f"(hi) : "l"(v));
    return lo + hi;
}
__device__ __forceinline__ float sigmoidf_(float x) { return 1.0f / (1.0f + expf(-x)); }
__device__ __forceinline__ uint32_t smem_u32(const void* p) {
    uint32_t a;
    asm("{ .reg .u64 t; cvta.to.shared.u64 t, %1; cvt.u32.u64 %0, t; }" : "=r"(a) : "l"(p));
    return a;
}
__device__ __forceinline__ void ldsm4(uint32_t* r, uint32_t a) {
    asm volatile("ldmatrix.sync.aligned.m8n8.x4.shared.b16 {%0,%1,%2,%3}, [%4];"
        : "=r"(r[0]),"=r"(r[1]),"=r"(r[2]),"=r"(r[3]) : "r"(a));
}
__device__ __forceinline__ void mma16816(float* c, const uint32_t* a, const uint32_t* b) {
    asm volatile("mma.sync.aligned.m16n8k16.row.col.f32.f16.f16.f32 "
        "{%0,%1,%2,%3}, {%4,%5,%6,%7}, {%8,%9}, {%0,%1,%2,%3};"
        : "+f"(c[0]),"+f"(c[1]),"+f"(c[2]),"+f"(c[3])
        : "r"(a[0]),"r"(a[1]),"r"(a[2]),"r"(a[3]),"r"(b[0]),"r"(b[1]));
}
#define CPA16(d, s) asm volatile("cp.async.cg.shared.global [%0], [%1], 16;" :: "r"(d), "l"(s))
#define CPCOMMIT()  asm volatile("cp.async.commit_group;")
#define CPWAIT0()   asm volatile("cp.async.wait_group 0;")

__global__ void pack_pred(const float* __restrict__ h2o_w, float* __restrict__ WPRED) {
    int g2 = blockIdx.x * blockDim.x + threadIdx.x;
    if (g2 >= 2048) return;
    int k2 = g2 >> 5, o = g2 & 31;
    WPRED[g2*2]   = h2o_w[(size_t)(2*k2)*32+o];
    WPRED[g2*2+1] = h2o_w[(size_t)(2*k2+1)*32+o];
}
__device__ __forceinline__ void pack_gate(const float* wh, const float* wi, unsigned char* W,
                                          int c, int n) {
    int gate = n >> 7, j = n & 127;
    for (int s = 0; s < 4; s++) {
        __half seg[8];
        for (int i = 0; i < 8; i++) {
            int gk = c*32 + s*8 + i;
            float w;
            if      (gate == 0) w = gk < 128 ? wh[(size_t)gk*128 + j] : wi[(size_t)(gk-128)*128 + j];
            else if (gate == 1) w = gk < 128 ? wh[16384 + (size_t)gk*128 + j] : wi[4096 + (size_t)(gk-128)*128 + j];
            else if (gate == 2) w = gk < 128 ? wh[32768 + (size_t)gk*128 + j] : 0.0f;
            else                w = gk < 128 ? 0.0f : wi[8192 + (size_t)(gk-128)*128 + j];
            seg[i] = __float2half_rn(w);
        }
        size_t off = (size_t)c*32768 + (size_t)n*64 + (size_t)((s + (n>>1)) & 3)*16;
        *(float4*)(W + off) = *(const float4*)seg;
    }
}
__global__ void pack_wtc(const float* __restrict__ awh, const float* __restrict__ awi,
                         const float* __restrict__ fwh, const float* __restrict__ fwi,
                         const float* __restrict__ ufw, const float* __restrict__ uaw,
                         unsigned char* __restrict__ WTC, unsigned char* __restrict__ WTCF,
                         unsigned char* __restrict__ WU) {
    int id = blockIdx.x * blockDim.x + threadIdx.x;
    if (id < 2560)      pack_gate(awh, awi, WTC,  id / 512, id % 512);
    else if (id < 5120) pack_gate(fwh, fwi, WTCF, (id-2560) / 512, (id-2560) % 512);
    else if (id < 6144) {
        int q = id - 5120, c = q >> 7, n = q & 127;
        const float* W = (c < 4) ? ufw : uaw;
        int kb = (c & 3) * 32;
        for (int s = 0; s < 4; s++) {
            __half seg[8];
            for (int i = 0; i < 8; i++)
                seg[i] = __float2half_rn(W[(size_t)(kb + s*8 + i)*128 + n]);
            size_t off = (size_t)c*8192 + (size_t)n*64 + (size_t)((s + (n>>1)) & 3)*16;
            *(float4*)(WU + off) = *(const float4*)seg;
        }
    }
}

__global__ void __launch_bounds__(NTHR)
init_kernel(const float* __restrict__ z, const float* __restrict__ w,
            const float* __restrict__ b, float* __restrict__ hout) {
    __shared__ float zs[RB][INdim];
    const int j = threadIdx.x, row0 = blockIdx.x * RB;
    {
        const float4* src = reinterpret_cast<const float4*>(z + (size_t)row0 * INdim);
        float4* dst = reinterpret_cast<float4*>(&zs[0][0]);
        for (int i = j; i < RB * INdim / 4; i += NTHR) dst[i] = src[i];
    }
    __syncthreads();
    const float bb = b[j];
    float acc[RB];
#pragma unroll
    for (int i = 0; i < RB; i++) acc[i] = bb;
#pragma unroll 4
    for (int k = 0; k < INdim; k += 4) {
        float4 hv[RB];
#pragma unroll
        for (int i = 0; i < RB; i++) hv[i] = *reinterpret_cast<const float4*>(&zs[i][k]);
#pragma unroll
        for (int kk = 0; kk < 4; kk++) {
            float wv = w[(size_t)(k+kk)*Hdim + j];
#pragma unroll
            for (int i = 0; i < RB; i++) {
                float h = (kk==0)?hv[i].x:(kk==1)?hv[i].y:(kk==2)?hv[i].z:hv[i].w;
                acc[i] += h * wv;
            }
        }
    }
#pragma unroll
    for (int i = 0; i < RB; i++) hout[(size_t)(row0+i)*Hdim + j] = acc[i];
}

#define SM_AHI  0
#define SM_ALO  21504
#define SM_B    43008
#define SMEM_TC 206848
#define APITCH  336

__device__ __forceinline__ void load_h_tiles(unsigned char* smem, const float* __restrict__ h,
                                             int row0, int t) {
    for (int i = t; i < 2048; i += 512) {
        int row = i >> 5, k4 = i & 31;
        float4 v = ((const float4*)(h + (size_t)(row0+row)*Hdim))[k4];
        __half2 h01 = __floats2half2_rn(v.x, v.y);
        __half2 h23 = __floats2half2_rn(v.z, v.w);
        __half2 l01 = __floats2half2_rn(v.x - __half2float(h01.x), v.y - __half2float(h01.y));
        __half2 l23 = __floats2half2_rn(v.z - __half2float(h23.x), v.w - __half2float(h23.y));
        uint32_t o = (uint32_t)row*APITCH + k4*8;
        *(__half2*)(smem + SM_AHI + o)     = h01;
        *(__half2*)(smem + SM_AHI + o + 4) = h23;
        *(__half2*)(smem + SM_ALO + o)     = l01;
        *(__half2*)(smem + SM_ALO + o + 4) = l23;
    }
}
// prefetch ALL 5 chunks (160KB) into SM_B.. via cp.async (20 x 16B per thread)
__device__ __forceinline__ void prefetch_w(uint32_t sb, const unsigned char* __restrict__ W, int t) {
#pragma unroll
    for (int c = 0; c < 5; c++) {
        uint32_t dst = sb + SM_B + (uint32_t)c*32768u + (uint32_t)t*64u;
        const unsigned char* s0 = W + (size_t)c*32768 + (size_t)t*64;
#pragma unroll
        for (int q = 0; q < 4; q++) CPA16(dst + q*16, s0 + q*16);
    }
    CPCOMMIT();
}
// barrier-free mma stream over 5 resident chunks
__device__ __forceinline__ void gate_mma(uint32_t sb, int t, int wm, int wn, int lane,
                                         float acc[2][8][4]) {
    const uint32_t abase = sb + SM_AHI + (uint32_t)(wm*32 + (lane & 15))*APITCH + (uint32_t)(lane >> 4)*16;
    const int roffB = ((lane >> 4) << 3) + (lane & 7);
    const int sgB   = (lane >> 3) & 1;
#pragma unroll
    for (int c = 0; c < 5; c++) {
        uint32_t bbuf = sb + SM_B + (uint32_t)c*32768u;
#pragma unroll
        for (int kk = 0; kk < 2; kk++) {
            uint32_t ah[2][4], al[2][4];
#pragma unroll
            for (int tm = 0; tm < 2; tm++) {
                ldsm4(ah[tm], abase + (uint32_t)tm*16u*APITCH + (uint32_t)(c*32 + kk*16)*2);
                ldsm4(al[tm], abase + 21504u + (uint32_t)tm*16u*APITCH + (uint32_t)(c*32 + kk*16)*2);
            }
#pragma unroll
            for (int tn2 = 0; tn2 < 4; tn2++) {
                int n = wn*64 + tn2*16 + roffB;
                uint32_t ba = bbuf + (uint32_t)n*64u + (uint32_t)(((2*kk + sgB + (n>>1)) & 3))*16u;
                uint32_t b[4];
                ldsm4(b, ba);
#pragma unroll
                for (int tm = 0; tm < 2; tm++) {
                    mma16816(acc[tm][tn2*2],   ah[tm], b);
                    mma16816(acc[tm][tn2*2+1], ah[tm], b+2);
                    mma16816(acc[tm][tn2*2],   al[tm], b);
                    mma16816(acc[tm][tn2*2+1], al[tm], b+2);
                }
            }
        }
    }
    __syncthreads();
}
__device__ __forceinline__ void gate_epilogue(unsigned char* smem, float acc[2][8][4],
                                              const float* __restrict__ habs,
                                              const float* __restrict__ abi, const float* __restrict__ abh,
                                              int row0, int t, int wm, int wn, int lane,
                                              float hprime[16]) {
    float* exch = (float*)smem;
    const int row = t >> 3, j0 = (t & 7)*16;
    float rg[16], zg[16];
    if (wn < 4) {
        int gsel = wn >> 1;
#pragma unroll
        for (int tm = 0; tm < 2; tm++)
#pragma unroll
            for (int tn = 0; tn < 8; tn++) {
                int col = (wn & 1)*64 + tn*8 + 2*(lane & 3);
                int r1 = wm*32 + tm*16 + (lane >> 2);
                *(float2*)&exch[gsel*8448 + r1*132 + col]     = make_float2(acc[tm][tn][0], acc[tm][tn][1]);
                *(float2*)&exch[gsel*8448 + (r1+8)*132 + col] = make_float2(acc[tm][tn][2], acc[tm][tn][3]);
            }
    }
    __syncthreads();
#pragma unroll
    for (int b = 0; b < 4; b++) {
        int j = j0 + b*4;
        float4 vr = *(const float4*)&exch[row*132 + j];
        float4 vz = *(const float4*)&exch[8448 + row*132 + j];
        float4 bir = *(const float4*)&abi[j],     bhr = *(const float4*)&abh[j];
        float4 biz = *(const float4*)&abi[128+j], bhz = *(const float4*)&abh[128+j];
        const float *pr = (const float*)&vr, *pz = (const float*)&vz;
        const float *b1 = (const float*)&bir, *b2 = (const float*)&bhr;
        const float *b3 = (const float*)&biz, *b4 = (const float*)&bhz;
#pragma unroll
        for (int e = 0; e < 4; e++) {
            rg[b*4+e] = sigmoidf_(pr[e] + b1[e] + b2[e]);
            zg[b*4+e] = sigmoidf_(pz[e] + b3[e] + b4[e]);
        }
    }
    __syncthreads();
    if (wn >= 4) {
        int gsel = (wn - 4) >> 1;
#pragma unroll
        for (int tm = 0; tm < 2; tm++)
#pragma unroll
            for (int tn = 0; tn < 8; tn++) {
                int col = (wn & 1)*64 + tn*8 + 2*(lane & 3);
                int r1 = wm*32 + tm*16 + (lane >> 2);
                *(float2*)&exch[gsel*8448 + r1*132 + col]     = make_float2(acc[tm][tn][0], acc[tm][tn][1]);
                *(float2*)&exch[gsel*8448 + (r1+8)*132 + col] = make_float2(acc[tm][tn][2], acc[tm][tn][3]);
            }
    }
    __syncthreads();
#pragma unroll
    for (int b = 0; b < 4; b++) {
        int j = j0 + b*4;
        float4 vh = *(const float4*)&exch[row*132 + j];
        float4 vx = *(const float4*)&exch[8448 + row*132 + j];
        float4 bin = *(const float4*)&abi[256+j], bhn = *(const float4*)&abh[256+j];
        float4 hv = *(const float4*)(habs + (size_t)(row0+row)*Hdim + j);
        const float *ph = (const float*)&vh, *px = (const float*)&vx;
        const float *bn = (const float*)&bin, *hn = (const float*)&bhn;
        const float *pv = (const float*)&hv;
#pragma unroll
        for (int e = 0; e < 4; e++) {
            float nn = tanhf(px[e] + bn[e] + rg[b*4+e]*(ph[e] + hn[e]));
            hprime[b*4+e] = (1.0f - zg[b*4+e])*nn + zg[b*4+e]*pv[e];
        }
    }
}

// ======== node kernel ========
__global__ void __launch_bounds__(512, 1)
node_tc(const float* __restrict__ h_a,
        const float* __restrict__ wpred, const float* __restrict__ h2o_b,
        const unsigned char* __restrict__ WTC,
        const float* __restrict__ abi, const float* __restrict__ abh,
        float* __restrict__ pred_out, float* __restrict__ probs_out,
        float* __restrict__ h_out) {
    extern __shared__ __align__(128) unsigned char smem[];
    const uint32_t sb = smem_u32(smem);
    const int t = threadIdx.x, wid = t >> 5, lane = t & 31;
    const int row0 = blockIdx.x * 64;

    prefetch_w(sb, WTC, t);
    load_h_tiles(smem, h_a, row0, t);
    {
        const float bo = h2o_b[lane];
        const u64* WPp = (const u64*)wpred;
        for (int rr = 0; rr < 4; rr++) {
            int row = wid*4 + rr, grow = row0 + row;
            const u64* hr = (const u64*)(h_a + (size_t)grow*Hdim);
            u64 acc = pack2(bo, 0.0f);
#pragma unroll 8
            for (int k2 = 0; k2 < 64; k2++) ffma2(acc, hr[k2], WPp[k2*32 + lane]);
            float v = f2sum(acc), m = v;
#pragma unroll
            for (int s = 16; s > 0; s >>= 1) m = fmaxf(m, __shfl_xor_sync(~0u, m, s));
            float e = expf(v - m), ss = e;
#pragma unroll
            for (int s = 16; s > 0; s >>= 1) ss += __shfl_xor_sync(~0u, ss, s);
            float p = e / ss;
            pred_out[(size_t)grow*Odim + lane]  = v;
            probs_out[(size_t)grow*Odim + lane] = p;
            __half ph = __float2half_rn(p);
            __half pl = __float2half_rn(p - __half2float(ph));
            uint32_t o = (uint32_t)row*APITCH + 256 + 2*lane;
            *(__half*)(smem + SM_AHI + o) = ph;
            *(__half*)(smem + SM_ALO + o) = pl;
        }
    }
    CPWAIT0();
    __syncthreads();

    const int wm = wid & 1, wn = wid >> 1;
    float acc[2][8][4];
#pragma unroll
    for (int a = 0; a < 2; a++)
#pragma unroll
        for (int i = 0; i < 8; i++)
#pragma unroll
            for (int q = 0; q < 4; q++) acc[a][i][q] = 0.0f;
    gate_mma(sb, t, wm, wn, lane, acc);
    float hp[16];
    gate_epilogue(smem, acc, h_a, abi, abh, row0, t, wm, wn, lane, hp);
    {
        const int row = t >> 3, j0 = (t & 7)*16;
        float* po = h_out + (size_t)(row0+row)*Hdim + j0;
#pragma unroll
        for (int q = 0; q < 4; q++)
            *(float4*)(po + q*4) = make_float4(hp[q*4], hp[q*4+1], hp[q*4+2], hp[q*4+3]);
    }
}

// ======== combine kernel ========
__global__ void __launch_bounds__(512, 1)
combine_tc(const float* __restrict__ probs_fc,
           const float* __restrict__ h_ai, const float* __restrict__ h_a,
           const unsigned char* __restrict__ WTCF,
           const float* __restrict__ fbi, const float* __restrict__ fbh,
           const unsigned char* __restrict__ WU,
           const float* __restrict__ ufb, const float* __restrict__ uab,
           float* __restrict__ h2_out) {
    extern __shared__ __align__(128) unsigned char smem[];
    const uint32_t sb = smem_u32(smem);
    const int t = threadIdx.x, lane = t & 31, wid = t >> 5;
    const int wm = wid & 1, wn = wid >> 1;
    const int row0 = blockIdx.x * 64;

    prefetch_w(sb, WTCF, t);
    load_h_tiles(smem, h_ai, row0, t);
    {
#pragma unroll
        for (int q = 0; q < 4; q++) {
            int idx = t*4 + q, row = idx >> 5, c = idx & 31;
            float p = probs_fc[(size_t)(row0+row)*Odim + c];
            __half ph = __float2half_rn(p);
            __half pl = __float2half_rn(p - __half2float(ph));
            uint32_t o = (uint32_t)row*APITCH + 256 + 2*c;
            *(__half*)(smem + SM_AHI + o) = ph;
            *(__half*)(smem + SM_ALO + o) = pl;
        }
    }
    CPWAIT0();
    __syncthreads();

    float acc[2][8][4];
#pragma unroll
    for (int a = 0; a < 2; a++)
#pragma unroll
        for (int i = 0; i < 8; i++)
#pragma unroll
            for (int q = 0; q < 4; q++) acc[a][i][q] = 0.0f;
    gate_mma(sb, t, wm, wn, lane, acc);
    float hf[16];
    gate_epilogue(smem, acc, h_ai, fbi, fbh, row0, t, wm, wn, lane, hf);
    __syncthreads();

    {   // hf -> A tiles
        const int row = t >> 3, j0 = (t & 7)*16;
#pragma unroll
        for (int q = 0; q < 8; q++) {
            float a0 = hf[q*2], a1 = hf[q*2+1];
            __half2 hh = __floats2half2_rn(a0, a1);
            __half2 ll = __floats2half2_rn(a0 - __half2float(hh.x), a1 - __half2float(hh.y));
            uint32_t o = (uint32_t)row*APITCH + (j0 + q*2)*2;
            *(__half2*)(smem + SM_AHI + o) = hh;
            *(__half2*)(smem + SM_ALO + o) = ll;
        }
    }
    __syncthreads();

    float acc2[2][2][4];
#pragma unroll
    for (int a = 0; a < 2; a++)
#pragma unroll
        for (int i = 0; i < 2; i++)
#pragma unroll
            for (int q = 0; q < 4; q++) acc2[a][i][q] = 0.0f;

    const uint32_t abase = sb + SM_AHI + (uint32_t)(wm*32 + (lane & 15))*APITCH + (uint32_t)(lane >> 4)*16;
    const int roffB = ((lane >> 4) << 3) + (lane & 7);
    const int sgB   = (lane >> 3) & 1;

    for (int ph = 0; ph < 2; ph++) {
        if (ph == 1) {
            __syncthreads();
            load_h_tiles(smem, h_a, row0, t);
        }
        // resident load of 4 merge chunks (32KB) into SM_B
        {
            if (t < 128) {
#pragma unroll
                for (int c2 = 0; c2 < 4; c2++) {
                    uint32_t dst = sb + SM_B + (uint32_t)c2*8192u + (uint32_t)t*64u;
                    const unsigned char* s0 = WU + (size_t)(ph*4 + c2)*8192 + (size_t)t*64;
#pragma unroll
                    for (int q = 0; q < 4; q++) CPA16(dst + q*16, s0 + q*16);
                }
            }
            CPCOMMIT(); CPWAIT0();
            __syncthreads();
        }
#pragma unroll
        for (int c2 = 0; c2 < 4; c2++) {
#pragma unroll
            for (int kk = 0; kk < 2; kk++) {
                uint32_t ah[2][4], al[2][4];
#pragma unroll
                for (int tm = 0; tm < 2; tm++) {
                    ldsm4(ah[tm], abase + (uint32_t)tm*16u*APITCH + (uint32_t)(c2*32 + kk*16)*2);
                    ldsm4(al[tm], abase + 21504u + (uint32_t)tm*16u*APITCH + (uint32_t)(c2*32 + kk*16)*2);
                }
                int n = wn*16 + roffB;
                uint32_t ba = sb + SM_B + (uint32_t)c2*8192u + (uint32_t)n*64u
                            + (uint32_t)(((2*kk + sgB + (n>>1)) & 3))*16u;
                uint32_t b[4];
                ldsm4(b, ba);
#pragma unroll
                for (int tm = 0; tm < 2; tm++) {
                    mma16816(acc2[tm][0], ah[tm], b);
                    mma16816(acc2[tm][1], ah[tm], b+2);
                    mma16816(acc2[tm][0], al[tm], b);
                    mma16816(acc2[tm][1], al[tm], b+2);
                }
            }
        }
        __syncthreads();
    }

    {   // final exchange + tanh
        float* exch = (float*)smem;
#pragma unroll
        for (int tm = 0; tm < 2; tm++)
#pragma unroll
            for (int tn = 0; tn < 2; tn++) {
                int col = wn*16 + tn*8 + 2*(lane & 3);
                int r1 = wm*32 + tm*16 + (lane >> 2);
                *(float2*)&exch[r1*132 + col]     = make_float2(acc2[tm][tn][0], acc2[tm][tn][1]);
                *(float2*)&exch[(r1+8)*132 + col] = make_float2(acc2[tm][tn][2], acc2[tm][tn][3]);
            }
        __syncthreads();
        const int row = t >> 3, j0 = (t & 7)*16;
        float* po = h2_out + (size_t)(row0+row)*Hdim + j0;
#pragma unroll
        for (int b = 0; b < 4; b++) {
            int j = j0 + b*4;
            float4 v = *(const float4*)&exch[row*132 + j];
            float4 b1 = *(const float4*)&ufb[j], b2 = *(const float4*)&uab[j];
            float4 out;
            out.x = tanhf(v.x + b1.x + b2.x);
            out.y = tanhf(v.y + b1.y + b2.y);
            out.z = tanhf(v.z + b1.z + b2.z);
            out.w = tanhf(v.w + b1.w + b2.w);
            *(float4*)(po + b*4) = out;
        }
    }
}

// ======== host orchestration ========
struct EmitCtx {
    const float *wpred, *h2o_b, *abi, *abh, *fbi, *fbh, *uab, *ufb;
    const unsigned char *WTC, *WTCF, *WU;
    float *out, *HAI, *H2, *PR;
    int B, idx;
};

static void emit_node(EmitCtx& P, int lvl, int d, const float* h_in) {
    float* probs = P.PR  + (size_t)lvl * P.B * Odim;
    float* h_ai  = P.HAI + (size_t)lvl * P.B * Hdim;
    node_tc<<<P.B / 64, 512, SMEM_TC>>>(h_in, P.wpred, P.h2o_b, P.WTC, P.abi, P.abh,
                                        P.out + (size_t)P.idx * P.B * Odim, probs, h_ai);
    P.idx++;
    if (d > 0) {
        emit_node(P, lvl + 1, d - 1, h_ai);
        float* h2 = P.H2 + (size_t)lvl * P.B * Hdim;
        combine_tc<<<P.B / 64, 512, SMEM_TC>>>(P.PR + (size_t)(lvl+1) * P.B * Odim,
                                               h_ai, h_in, P.WTCF, P.fbi, P.fbh,
                                               P.WU, P.ufb, P.uab, h2);
        emit_node(P, lvl + 1, d - 1, h2);
    }
}

extern "C" void kernel_launch(void* const* d_in, const int* in_sizes, int n_in,
                              void* d_out, int out_size) {
    const float* z     = (const float*)d_in[0];
    const float* z2h_w = (const float*)d_in[1];
    const float* z2h_b = (const float*)d_in[2];
    const float* h2o_w = (const float*)d_in[3];
    const float* h2o_b = (const float*)d_in[4];
    const float* awi   = (const float*)d_in[5];
    const float* abi   = (const float*)d_in[6];
    const float* awh   = (const float*)d_in[7];
    const float* abh   = (const float*)d_in[8];
    const float* fwi   = (const float*)d_in[9];
    const float* fbi   = (const float*)d_in[10];
    const float* fwh   = (const float*)d_in[11];
    const float* fbh   = (const float*)d_in[12];
    const float* uaw   = (const float*)d_in[13];
    const float* uab   = (const float*)d_in[14];
    const float* ufw   = (const float*)d_in[15];
    const float* ufb   = (const float*)d_in[16];

    const int H  = in_sizes[2];
    const int O  = in_sizes[4];
    const int IN = in_sizes[1] / H;
    const int B  = in_sizes[0] / IN;
    const int nn = out_size / (B * O);
    int depth = 0;
    while (((2 << depth) - 1) < nn) depth++;

    float *H0p, *HAIp, *H2p, *PRp, *WPRp;
    unsigned char *WTCp, *WTCFp, *WUp;
    cudaGetSymbolAddress((void**)&H0p,  g_H0);
    cudaGetSymbolAddress((void**)&HAIp, g_HAI);
    cudaGetSymbolAddress((void**)&H2p,  g_H2);
    cudaGetSymbolAddress((void**)&PRp,  g_PR);
    cudaGetSymbolAddress((void**)&WPRp, g_WPRED);
    cudaGetSymbolAddress((void**)&WTCp, g_WTC);
    cudaGetSymbolAddress((void**)&WTCFp, g_WTCF);
    cudaGetSymbolAddress((void**)&WUp,  g_WU);

    cudaFuncSetAttribute(node_tc,    cudaFuncAttributeMaxDynamicSharedMemorySize, SMEM_TC);
    cudaFuncSetAttribute(combine_tc, cudaFuncAttributeMaxDynamicSharedMemorySize, SMEM_TC);

    pack_pred<<<(2048 + 255) / 256, 256>>>(h2o_w, WPRp);
    pack_wtc<<<(6144 + 127) / 128, 128>>>(awh, awi, fwh, fwi, ufw, uaw, WTCp, WTCFp, WUp);
    init_kernel<<<B / RB, NTHR>>>(z, z2h_w, z2h_b, H0p);

    EmitCtx P;
    P.wpred = WPRp; P.h2o_b = h2o_b;
    P.abi = abi; P.abh = abh; P.fbi = fbi; P.fbh = fbh;
    P.uab = uab; P.ufb = ufb;
    P.WTC = WTCp; P.WTCF = WTCFp; P.WU = WUp;
    P.out = (float*)d_out;
    P.HAI = HAIp; P.H2 = H2p; P.PR = PRp;
    P.B = B; P.idx = 0;

    emit_node(P, 0, depth, H0p);
}

// round 15
// speedup vs baseline: 1.2360x; 1.2360x over previous
#include <cuda_runtime.h>
#include <cuda_fp16.h>
#include <cstdint>

#define Hdim 128
#define Odim 32
#define INdim 64
#define RB 8
#define NTHR 128
#define MAXB 16384
#define MAXLVL 6

__device__ float g_H0 [(size_t)MAXB * Hdim];
__device__ float g_HAI[(size_t)MAXLVL * MAXB * Hdim];
__device__ float g_H2 [(size_t)MAXLVL * MAXB * Hdim];
__device__ float g_PR [(size_t)(MAXLVL + 1) * MAXB * Odim];

__device__ __align__(1024) unsigned char g_WTC [184320]; // node: [5][576n][64B]
__device__ __align__(1024) unsigned char g_WTCF[163840]; // gru_f: [5][512n][64B]
__device__ __align__(1024) unsigned char g_WU  [65536];  // uf;ua: [8][128n][64B]

typedef unsigned long long u64;

__device__ __forceinline__ float sigmoidf_(float x) { return 1.0f / (1.0f + expf(-x)); }
__device__ __forceinline__ uint32_t smem_u32(const void* p) {
    uint32_t a;
    asm("{ .reg .u64 t; cvta.to.shared.u64 t, %1; cvt.u32.u64 %0, t; }" : "=r"(a) : "l"(p));
    return a;
}
__device__ __forceinline__ void ldsm4(uint32_t* r, uint32_t a) {
    asm volatile("ldmatrix.sync.aligned.m8n8.x4.shared.b16 {%0,%1,%2,%3}, [%4];"
        : "=r"(r[0]),"=r"(r[1]),"=r"(r[2]),"=r"(r[3]) : "r"(a));
}
__device__ __forceinline__ void ldsm2(uint32_t* r, uint32_t a) {
    asm volatile("ldmatrix.sync.aligned.m8n8.x2.shared.b16 {%0,%1}, [%2];"
        : "=r"(r[0]),"=r"(r[1]) : "r"(a));
}
__device__ __forceinline__ void mma16816(float* c, const uint32_t* a, const uint32_t* b) {
    asm volatile("mma.sync.aligned.m16n8k16.row.col.f32.f16.f16.f32 "
        "{%0,%1,%2,%3}, {%4,%5,%6,%7}, {%8,%9}, {%0,%1,%2,%3};"
        : "+f"(c[0]),"+f"(c[1]),"+f"(c[2]),"+f"(c[3])
        : "r"(a[0]),"r"(a[1]),"r"(a[2]),"r"(a[3]),"r"(b[0]),"r"(b[1]));
}
#define CPA16(d, s) asm volatile("cp.async.cg.shared.global [%0], [%1], 16;" :: "r"(d), "l"(s))
#define CPCOMMIT()  asm volatile("cp.async.commit_group;")
#define CPWAIT0()   asm volatile("cp.async.wait_group 0;")

// pack one 64B row: node image (576 rows incl pred cols) or gate-only (512)
__global__ void pack_wtc(const float* __restrict__ awh, const float* __restrict__ awi,
                         const float* __restrict__ fwh, const float* __restrict__ fwi,
                         const float* __restrict__ ufw, const float* __restrict__ uaw,
                         const float* __restrict__ h2o_w,
                         unsigned char* __restrict__ WTC, unsigned char* __restrict__ WTCF,
                         unsigned char* __restrict__ WU) {
    int id = blockIdx.x * blockDim.x + threadIdx.x;
    const float *wh, *wi;
    unsigned char* dst;
    int c, n, cs;
    if (id < 2880)      { c = id / 576;        n = id % 576;        wh = awh; wi = awi; dst = WTC;  cs = 36864; }
    else if (id < 5440) { c = (id-2880) / 512; n = (id-2880) % 512; wh = fwh; wi = fwi; dst = WTCF; cs = 32768; }
    else if (id < 6464) {
        int q = id - 5440; c = q >> 7; n = q & 127;
        const float* W = (c < 4) ? ufw : uaw;
        int kb = (c & 3) * 32;
        for (int s = 0; s < 4; s++) {
            __half seg[8];
            for (int i = 0; i < 8; i++)
                seg[i] = __float2half_rn(W[(size_t)(kb + s*8 + i)*128 + n]);
            size_t off = (size_t)c*8192 + (size_t)n*64 + (size_t)((s + (n>>1)) & 3)*16;
            *(float4*)(WU + off) = *(const float4*)seg;
        }
        return;
    } else return;
    for (int s = 0; s < 4; s++) {
        __half seg[8];
        for (int i = 0; i < 8; i++) {
            int gk = c*32 + s*8 + i;
            float w; __half hv;
            if (n < 512) {
                int gate = n >> 7, j = n & 127;
                if      (gate == 0) w = gk < 128 ? wh[(size_t)gk*128 + j] : wi[(size_t)(gk-128)*128 + j];
                else if (gate == 1) w = gk < 128 ? wh[16384 + (size_t)gk*128 + j] : wi[4096 + (size_t)(gk-128)*128 + j];
                else if (gate == 2) w = gk < 128 ? wh[32768 + (size_t)gk*128 + j] : 0.0f;
                else                w = gk < 128 ? 0.0f : wi[8192 + (size_t)(gk-128)*128 + j];
                hv = __float2half_rn(w);
            } else {
                int o = (n - 512) >> 1, pl = (n - 512) & 1;
                if (gk < 128) {
                    float f = h2o_w[(size_t)gk*32 + o];
                    __half hi = __float2half_rn(f);
                    hv = pl ? __float2half_rn(f - __half2float(hi)) : hi;
                } else hv = __float2half_rn(0.0f);
            }
            seg[i] = hv;
        }
        size_t off = (size_t)c*cs + (size_t)n*64 + (size_t)((s + (n>>1)) & 3)*16;
        *(float4*)(dst + off) = *(const float4*)seg;
    }
}

__global__ void __launch_bounds__(NTHR)
init_kernel(const float* __restrict__ z, const float* __restrict__ w,
            const float* __restrict__ b, float* __restrict__ hout) {
    __shared__ float zs[RB][INdim];
    const int j = threadIdx.x, row0 = blockIdx.x * RB;
    {
        const float4* src = reinterpret_cast<const float4*>(z + (size_t)row0 * INdim);
        float4* dst = reinterpret_cast<float4*>(&zs[0][0]);
        for (int i = j; i < RB * INdim / 4; i += NTHR) dst[i] = src[i];
    }
    __syncthreads();
    const float bb = b[j];
    float acc[RB];
#pragma unroll
    for (int i = 0; i < RB; i++) acc[i] = bb;
#pragma unroll 4
    for (int k = 0; k < INdim; k += 4) {
        float4 hv[RB];
#pragma unroll
        for (int i = 0; i < RB; i++) hv[i] = *reinterpret_cast<const float4*>(&zs[i][k]);
#pragma unroll
        for (int kk = 0; kk < 4; kk++) {
            float wv = w[(size_t)(k+kk)*Hdim + j];
#pragma unroll
            for (int i = 0; i < RB; i++) {
                float h = (kk==0)?hv[i].x:(kk==1)?hv[i].y:(kk==2)?hv[i].z:hv[i].w;
                acc[i] += h * wv;
            }
        }
    }
#pragma unroll
    for (int i = 0; i < RB; i++) hout[(size_t)(row0+i)*Hdim + j] = acc[i];
}

#define SM_AHI  0
#define SM_ALO  21504
#define SM_B    43008
#define SM_X    190464
#define SMEM_TCN 223232
#define SMEM_TCC 206848
#define APITCH  336

__device__ __forceinline__ void load_h_tiles(unsigned char* smem, const float* __restrict__ h,
                                             int row0, int t) {
    for (int i = t; i < 2048; i += 512) {
        int row = i >> 5, k4 = i & 31;
        float4 v = ((const float4*)(h + (size_t)(row0+row)*Hdim))[k4];
        __half2 h01 = __floats2half2_rn(v.x, v.y);
        __half2 h23 = __floats2half2_rn(v.z, v.w);
        __half2 l01 = __floats2half2_rn(v.x - __half2float(h01.x), v.y - __half2float(h01.y));
        __half2 l23 = __floats2half2_rn(v.z - __half2float(h23.x), v.w - __half2float(h23.y));
        uint32_t o = (uint32_t)row*APITCH + k4*8;
        *(__half2*)(smem + SM_AHI + o)     = h01;
        *(__half2*)(smem + SM_AHI + o + 4) = h23;
        *(__half2*)(smem + SM_ALO + o)     = l01;
        *(__half2*)(smem + SM_ALO + o + 4) = l23;
    }
}
__device__ __forceinline__ void gate_epilogue(unsigned char* smem, float acc[2][8][4],
                                              const float* __restrict__ habs,
                                              const float* __restrict__ abi, const float* __restrict__ abh,
                                              int row0, int t, int wm, int wn, int lane,
                                              float hprime[16]) {
    float* exch = (float*)smem;
    const int row = t >> 3, j0 = (t & 7)*16;
    float rg[16], zg[16];
    if (wn < 4) {
        int gsel = wn >> 1;
#pragma unroll
        for (int tm = 0; tm < 2; tm++)
#pragma unroll
            for (int tn = 0; tn < 8; tn++) {
                int col = (wn & 1)*64 + tn*8 + 2*(lane & 3);
                int r1 = wm*32 + tm*16 + (lane >> 2);
                *(float2*)&exch[gsel*8448 + r1*132 + col]     = make_float2(acc[tm][tn][0], acc[tm][tn][1]);
                *(float2*)&exch[gsel*8448 + (r1+8)*132 + col] = make_float2(acc[tm][tn][2], acc[tm][tn][3]);
            }
    }
    __syncthreads();
#pragma unroll
    for (int b = 0; b < 4; b++) {
        int j = j0 + b*4;
        float4 vr = *(const float4*)&exch[row*132 + j];
        float4 vz = *(const float4*)&exch[8448 + row*132 + j];
        float4 bir = *(const float4*)&abi[j],     bhr = *(const float4*)&abh[j];
        float4 biz = *(const float4*)&abi[128+j], bhz = *(const float4*)&abh[128+j];
        const float *pr = (const float*)&vr, *pz = (const float*)&vz;
        const float *b1 = (const float*)&bir, *b2 = (const float*)&bhr;
        const float *b3 = (const float*)&biz, *b4 = (const float*)&bhz;
#pragma unroll
        for (int e = 0; e < 4; e++) {
            rg[b*4+e] = sigmoidf_(pr[e] + b1[e] + b2[e]);
            zg[b*4+e] = sigmoidf_(pz[e] + b3[e] + b4[e]);
        }
    }
    __syncthreads();
    if (wn >= 4) {
        int gsel = (wn - 4) >> 1;
#pragma unroll
        for (int tm = 0; tm < 2; tm++)
#pragma unroll
            for (int tn = 0; tn < 8; tn++) {
                int col = (wn & 1)*64 + tn*8 + 2*(lane & 3);
                int r1 = wm*32 + tm*16 + (lane >> 2);
                *(float2*)&exch[gsel*8448 + r1*132 + col]     = make_float2(acc[tm][tn][0], acc[tm][tn][1]);
                *(float2*)&exch[gsel*8448 + (r1+8)*132 + col] = make_float2(acc[tm][tn][2], acc[tm][tn][3]);
            }
    }
    __syncthreads();
#pragma unroll
    for (int b = 0; b < 4; b++) {
        int j = j0 + b*4;
        float4 vh = *(const float4*)&exch[row*132 + j];
        float4 vx = *(const float4*)&exch[8448 + row*132 + j];
        float4 bin = *(const float4*)&abi[256+j], bhn = *(const float4*)&abh[256+j];
        float4 hv = *(const float4*)(habs + (size_t)(row0+row)*Hdim + j);
        const float *ph = (const float*)&vh, *px = (const float*)&vx;
        const float *bn = (const float*)&bin, *hn = (const float*)&bhn;
        const float *pv = (const float*)&hv;
#pragma unroll
        for (int e = 0; e < 4; e++) {
            float nn = tanhf(px[e] + bn[e] + rg[b*4+e]*(ph[e] + hn[e]));
            hprime[b*4+e] = (1.0f - zg[b*4+e])*nn + zg[b*4+e]*pv[e];
        }
    }
}

// ======== node kernel: gates+pred fused on tensor pipe ========
__global__ void __launch_bounds__(512, 1)
node_tc(const float* __restrict__ h_a, const float* __restrict__ h2o_b,
        const unsigned char* __restrict__ WTC,
        const float* __restrict__ abi, const float* __restrict__ abh,
        float* __restrict__ pred_out, float* __restrict__ probs_out,
        float* __restrict__ h_out) {
    extern __shared__ __align__(128) unsigned char smem[];
    const uint32_t sb = smem_u32(smem);
    const int t = threadIdx.x, wid = t >> 5, lane = t & 31;
    const int row0 = blockIdx.x * 64;

    // prefetch chunks 0-3 (147456B)
    for (uint32_t off = (uint32_t)t*16; off < 147456u; off += 8192u)
        CPA16(sb + SM_B + off, WTC + off);
    CPCOMMIT();
    load_h_tiles(smem, h_a, row0, t);
    CPWAIT0();
    __syncthreads();

    const int wm = wid & 1, wn = wid >> 1;
    float acc[2][8][4], accp[2][4];
#pragma unroll
    for (int a = 0; a < 2; a++) {
#pragma unroll
        for (int i = 0; i < 8; i++)
#pragma unroll
            for (int q = 0; q < 4; q++) acc[a][i][q] = 0.0f;
#pragma unroll
        for (int q = 0; q < 4; q++) accp[a][q] = 0.0f;
    }
    const uint32_t abase = sb + SM_AHI + (uint32_t)(wm*32 + (lane & 15))*APITCH + (uint32_t)(lane >> 4)*16;
    const int roffB = ((lane >> 4) << 3) + (lane & 7);
    const int sgB   = (lane >> 3) & 1;
    const int prow  = 512 + wn*8 + (lane & 7);

    // phase A: chunks 0-3 (k=0..127), gates + pred
#pragma unroll
    for (int c = 0; c < 4; c++) {
        uint32_t bbuf = sb + SM_B + (uint32_t)c*36864u;
#pragma unroll
        for (int kk = 0; kk < 2; kk++) {
            uint32_t ah[2][4], al[2][4];
#pragma unroll
            for (int tm = 0; tm < 2; tm++) {
                ldsm4(ah[tm], abase + (uint32_t)tm*16u*APITCH + (uint32_t)(c*32 + kk*16)*2);
                ldsm4(al[tm], abase + 21504u + (uint32_t)tm*16u*APITCH + (uint32_t)(c*32 + kk*16)*2);
            }
#pragma unroll
            for (int tn2 = 0; tn2 < 4; tn2++) {
                int n = wn*64 + tn2*16 + roffB;
                uint32_t ba = bbuf + (uint32_t)n*64u + (uint32_t)(((2*kk + sgB + (n>>1)) & 3))*16u;
                uint32_t b[4];
                ldsm4(b, ba);
#pragma unroll
                for (int tm = 0; tm < 2; tm++) {
                    mma16816(acc[tm][tn2*2],   ah[tm], b);
                    mma16816(acc[tm][tn2*2+1], ah[tm], b+2);
                    mma16816(acc[tm][tn2*2],   al[tm], b);
                    mma16816(acc[tm][tn2*2+1], al[tm], b+2);
                }
            }
            {   // pred n8 tile (rows 512 + wn*8 ..)
                uint32_t ba = bbuf + (uint32_t)prow*64u + (uint32_t)(((2*kk + sgB + (prow>>1)) & 3))*16u;
                uint32_t bp[2];
                ldsm2(bp, ba);
#pragma unroll
                for (int tm = 0; tm < 2; tm++) {
                    mma16816(accp[tm], ah[tm], bp);
                    mma16816(accp[tm], al[tm], bp);
                }
            }
        }
    }
    __syncthreads();

    // pred exchange into SM_X
    {
        float* predx = (float*)(smem + SM_X);
        const int o = 4*wn + (lane & 3);
#pragma unroll
        for (int tm = 0; tm < 2; tm++) {
            int r = wm*32 + tm*16 + (lane >> 2);
            predx[r*32 + o]     = accp[tm][0] + accp[tm][1];
            predx[(r+8)*32 + o] = accp[tm][2] + accp[tm][3];
        }
    }
    __syncthreads();

    // softmax: threads 0-63, streaming 3-pass
    if (t < 64) {
        const float* predx = (const float*)(smem + SM_X);
        const int grow = row0 + t;
        float m = -1e30f;
#pragma unroll
        for (int q = 0; q < 8; q++) {
            float4 v = ((const float4*)(predx + t*32))[q];
            float4 bb = ((const float4*)h2o_b)[q];
            v.x += bb.x; v.y += bb.y; v.z += bb.z; v.w += bb.w;
            ((float4*)(pred_out + (size_t)grow*Odim))[q] = v;
            m = fmaxf(m, fmaxf(fmaxf(v.x, v.y), fmaxf(v.z, v.w)));
        }
        float ss = 0.0f;
#pragma unroll
        for (int q = 0; q < 8; q++) {
            float4 v = ((const float4*)(predx + t*32))[q];
            float4 bb = ((const float4*)h2o_b)[q];
            ss += expf(v.x + bb.x - m) + expf(v.y + bb.y - m)
                + expf(v.z + bb.z - m) + expf(v.w + bb.w - m);
        }
        float inv = 1.0f / ss;
#pragma unroll
        for (int q = 0; q < 8; q++) {
            float4 v = ((const float4*)(predx + t*32))[q];
            float4 bb = ((const float4*)h2o_b)[q];
            float4 p;
            p.x = expf(v.x + bb.x - m) * inv;
            p.y = expf(v.y + bb.y - m) * inv;
            p.z = expf(v.z + bb.z - m) * inv;
            p.w = expf(v.w + bb.w - m) * inv;
            ((float4*)(probs_out + (size_t)grow*Odim))[q] = p;
            __half2 h01 = __floats2half2_rn(p.x, p.y);
            __half2 h23 = __floats2half2_rn(p.z, p.w);
            __half2 l01 = __floats2half2_rn(p.x - __half2float(h01.x), p.y - __half2float(h01.y));
            __half2 l23 = __floats2half2_rn(p.z - __half2float(h23.x), p.w - __half2float(h23.y));
            uint32_t o = (uint32_t)t*APITCH + 256 + q*8;
            *(__half2*)(smem + SM_AHI + o)     = h01;
            *(__half2*)(smem + SM_AHI + o + 4) = h23;
            *(__half2*)(smem + SM_ALO + o)     = l01;
            *(__half2*)(smem + SM_ALO + o + 4) = l23;
        }
    }
    __syncthreads();

    // chunk 4 (x-part, gate rows only) into SM_X
    {
        uint32_t dst = sb + SM_X + (uint32_t)t*64u;
        const unsigned char* s0 = WTC + 4*36864 + (size_t)t*64;
#pragma unroll
        for (int q = 0; q < 4; q++) CPA16(dst + q*16, s0 + q*16);
        CPCOMMIT(); CPWAIT0();
    }
    __syncthreads();

    // phase B: chunk 4 (k=128..159), gates only
    {
        const int c = 4;
        uint32_t bbuf = sb + SM_X;
#pragma unroll
        for (int kk = 0; kk < 2; kk++) {
            uint32_t ah[2][4], al[2][4];
#pragma unroll
            for (int tm = 0; tm < 2; tm++) {
                ldsm4(ah[tm], abase + (uint32_t)tm*16u*APITCH + (uint32_t)(c*32 + kk*16)*2);
                ldsm4(al[tm], abase + 21504u + (uint32_t)tm*16u*APITCH + (uint32_t)(c*32 + kk*16)*2);
            }
#pragma unroll
            for (int tn2 = 0; tn2 < 4; tn2++) {
                int n = wn*64 + tn2*16 + roffB;
                uint32_t ba = bbuf + (uint32_t)n*64u + (uint32_t)(((2*kk + sgB + (n>>1)) & 3))*16u;
                uint32_t b[4];
                ldsm4(b, ba);
#pragma unroll
                for (int tm = 0; tm < 2; tm++) {
                    mma16816(acc[tm][tn2*2],   ah[tm], b);
                    mma16816(acc[tm][tn2*2+1], ah[tm], b+2);
                    mma16816(acc[tm][tn2*2],   al[tm], b);
                    mma16816(acc[tm][tn2*2+1], al[tm], b+2);
                }
            }
        }
    }
    __syncthreads();

    float hp[16];
    gate_epilogue(smem, acc, h_a, abi, abh, row0, t, wm, wn, lane, hp);
    {
        const int row = t >> 3, j0 = (t & 7)*16;
        float* po = h_out + (size_t)(row0+row)*Hdim + j0;
#pragma unroll
        for (int q = 0; q < 4; q++)
            *(float4*)(po + q*4) = make_float4(hp[q*4], hp[q*4+1], hp[q*4+2], hp[q*4+3]);
    }
}

// ======== combine kernel (R14, proven) ========
__global__ void __launch_bounds__(512, 1)
combine_tc(const float* __restrict__ probs_fc,
           const float* __restrict__ h_ai, const float* __restrict__ h_a,
           const unsigned char* __restrict__ WTCF,
           const float* __restrict__ fbi, const float* __restrict__ fbh,
           const unsigned char* __restrict__ WU,
           const float* __restrict__ ufb, const float* __restrict__ uab,
           float* __restrict__ h2_out) {
    extern __shared__ __align__(128) unsigned char smem[];
    const uint32_t sb = smem_u32(smem);
    const int t = threadIdx.x, lane = t & 31, wid = t >> 5;
    const int wm = wid & 1, wn = wid >> 1;
    const int row0 = blockIdx.x * 64;

    for (uint32_t off = (uint32_t)t*16; off < 163840u; off += 8192u)
        CPA16(sb + SM_B + off, WTCF + off);
    CPCOMMIT();
    load_h_tiles(smem, h_ai, row0, t);
#pragma unroll
    for (int q = 0; q < 4; q++) {
        int idx = t*4 + q, row = idx >> 5, c = idx & 31;
        float p = probs_fc[(size_t)(row0+row)*Odim + c];
        __half ph = __float2half_rn(p);
        __half pl = __float2half_rn(p - __half2float(ph));
        uint32_t o = (uint32_t)row*APITCH + 256 + 2*c;
        *(__half*)(smem + SM_AHI + o) = ph;
        *(__half*)(smem + SM_ALO + o) = pl;
    }
    CPWAIT0();
    __syncthreads();

    float acc[2][8][4];
#pragma unroll
    for (int a = 0; a < 2; a++)
#pragma unroll
        for (int i = 0; i < 8; i++)
#pragma unroll
            for (int q = 0; q < 4; q++) acc[a][i][q] = 0.0f;

    const uint32_t abase = sb + SM_AHI + (uint32_t)(wm*32 + (lane & 15))*APITCH + (uint32_t)(lane >> 4)*16;
    const int roffB = ((lane >> 4) << 3) + (lane & 7);
    const int sgB   = (lane >> 3) & 1;
#pragma unroll
    for (int c = 0; c < 5; c++) {
        uint32_t bbuf = sb + SM_B + (uint32_t)c*32768u;
#pragma unroll
        for (int kk = 0; kk < 2; kk++) {
            uint32_t ah[2][4], al[2][4];
#pragma unroll
            for (int tm = 0; tm < 2; tm++) {
                ldsm4(ah[tm], abase + (uint32_t)tm*16u*APITCH + (uint32_t)(c*32 + kk*16)*2);
                ldsm4(al[tm], abase + 21504u + (uint32_t)tm*16u*APITCH + (uint32_t)(c*32 + kk*16)*2);
            }
#pragma unroll
            for (int tn2 = 0; tn2 < 4; tn2++) {
                int n = wn*64 + tn2*16 + roffB;
                uint32_t ba = bbuf + (uint32_t)n*64u + (uint32_t)(((2*kk + sgB + (n>>1)) & 3))*16u;
                uint32_t b[4];
                ldsm4(b, ba);
#pragma unroll
                for (int tm = 0; tm < 2; tm++) {
                    mma16816(acc[tm][tn2*2],   ah[tm], b);
                    mma16816(acc[tm][tn2*2+1], ah[tm], b+2);
                    mma16816(acc[tm][tn2*2],   al[tm], b);
                    mma16816(acc[tm][tn2*2+1], al[tm], b+2);
                }
            }
        }
    }
    __syncthreads();
    float hf[16];
    gate_epilogue(smem, acc, h_ai, fbi, fbh, row0, t, wm, wn, lane, hf);
    __syncthreads();

    {   // hf -> A tiles
        const int row = t >> 3, j0 = (t & 7)*16;
#pragma unroll
        for (int q = 0; q < 8; q++) {
            float a0 = hf[q*2], a1 = hf[q*2+1];
            __half2 hh = __floats2half2_rn(a0, a1);
            __half2 ll = __floats2half2_rn(a0 - __half2float(hh.x), a1 - __half2float(hh.y));
            uint32_t o = (uint32_t)row*APITCH + (j0 + q*2)*2;
            *(__half2*)(smem + SM_AHI + o) = hh;
            *(__half2*)(smem + SM_ALO + o) = ll;
        }
    }
    __syncthreads();

    float acc2[2][2][4];
#pragma unroll
    for (int a = 0; a < 2; a++)
#pragma unroll
        for (int i = 0; i < 2; i++)
#pragma unroll
            for (int q = 0; q < 4; q++) acc2[a][i][q] = 0.0f;

    for (int ph = 0; ph < 2; ph++) {
        if (ph == 1) {
            __syncthreads();
            load_h_tiles(smem, h_a, row0, t);
        }
        {
            if (t < 128) {
#pragma unroll
                for (int c2 = 0; c2 < 4; c2++) {
                    uint32_t dst = sb + SM_B + (uint32_t)c2*8192u + (uint32_t)t*64u;
                    const unsigned char* s0 = WU + (size_t)(ph*4 + c2)*8192 + (size_t)t*64;
#pragma unroll
                    for (int q = 0; q < 4; q++) CPA16(dst + q*16, s0 + q*16);
                }
            }
            CPCOMMIT(); CPWAIT0();
            __syncthreads();
        }
#pragma unroll
        for (int c2 = 0; c2 < 4; c2++) {
#pragma unroll
            for (int kk = 0; kk < 2; kk++) {
                uint32_t ah[2][4], al[2][4];
#pragma unroll
                for (int tm = 0; tm < 2; tm++) {
                    ldsm4(ah[tm], abase + (uint32_t)tm*16u*APITCH + (uint32_t)(c2*32 + kk*16)*2);
                    ldsm4(al[tm], abase + 21504u + (uint32_t)tm*16u*APITCH + (uint32_t)(c2*32 + kk*16)*2);
                }
                int n = wn*16 + roffB;
                uint32_t ba = sb + SM_B + (uint32_t)c2*8192u + (uint32_t)n*64u
                            + (uint32_t)(((2*kk + sgB + (n>>1)) & 3))*16u;
                uint32_t b[4];
                ldsm4(b, ba);
#pragma unroll
                for (int tm = 0; tm < 2; tm++) {
                    mma16816(acc2[tm][0], ah[tm], b);
                    mma16816(acc2[tm][1], ah[tm], b+2);
                    mma16816(acc2[tm][0], al[tm], b);
                    mma16816(acc2[tm][1], al[tm], b+2);
                }
            }
        }
        __syncthreads();
    }

    {
        float* exch = (float*)smem;
#pragma unroll
        for (int tm = 0; tm < 2; tm++)
#pragma unroll
            for (int tn = 0; tn < 2; tn++) {
                int col = wn*16 + tn*8 + 2*(lane & 3);
                int r1 = wm*32 + tm*16 + (lane >> 2);
                *(float2*)&exch[r1*132 + col]     = make_float2(acc2[tm][tn][0], acc2[tm][tn][1]);
                *(float2*)&exch[(r1+8)*132 + col] = make_float2(acc2[tm][tn][2], acc2[tm][tn][3]);
            }
        __syncthreads();
        const int row = t >> 3, j0 = (t & 7)*16;
        float* po = h2_out + (size_t)(row0+row)*Hdim + j0;
#pragma unroll
        for (int b = 0; b < 4; b++) {
            int j = j0 + b*4;
            float4 v = *(const float4*)&exch[row*132 + j];
            float4 b1 = *(const float4*)&ufb[j], b2 = *(const float4*)&uab[j];
            float4 out;
            out.x = tanhf(v.x + b1.x + b2.x);
            out.y = tanhf(v.y + b1.y + b2.y);
            out.z = tanhf(v.z + b1.z + b2.z);
            out.w = tanhf(v.w + b1.w + b2.w);
            *(float4*)(po + b*4) = out;
        }
    }
}

// ======== host orchestration ========
struct EmitCtx {
    const float *h2o_b, *abi, *abh, *fbi, *fbh, *uab, *ufb;
    const unsigned char *WTC, *WTCF, *WU;
    float *out, *HAI, *H2, *PR;
    int B, idx;
};

static void emit_node(EmitCtx& P, int lvl, int d, const float* h_in) {
    float* probs = P.PR  + (size_t)lvl * P.B * Odim;
    float* h_ai  = P.HAI + (size_t)lvl * P.B * Hdim;
    node_tc<<<P.B / 64, 512, SMEM_TCN>>>(h_in, P.h2o_b, P.WTC, P.abi, P.abh,
                                         P.out + (size_t)P.idx * P.B * Odim, probs, h_ai);
    P.idx++;
    if (d > 0) {
        emit_node(P, lvl + 1, d - 1, h_ai);
        float* h2 = P.H2 + (size_t)lvl * P.B * Hdim;
        combine_tc<<<P.B / 64, 512, SMEM_TCC>>>(P.PR + (size_t)(lvl+1) * P.B * Odim,
                                                h_ai, h_in, P.WTCF, P.fbi, P.fbh,
                                                P.WU, P.ufb, P.uab, h2);
        emit_node(P, lvl + 1, d - 1, h2);
    }
}

extern "C" void kernel_launch(void* const* d_in, const int* in_sizes, int n_in,
                              void* d_out, int out_size) {
    const float* z     = (const float*)d_in[0];
    const float* z2h_w = (const float*)d_in[1];
    const float* z2h_b = (const float*)d_in[2];
    const float* h2o_w = (const float*)d_in[3];
    const float* h2o_b = (const float*)d_in[4];
    const float* awi   = (const float*)d_in[5];
    const float* abi   = (const float*)d_in[6];
    const float* awh   = (const float*)d_in[7];
    const float* abh   = (const float*)d_in[8];
    const float* fwi   = (const float*)d_in[9];
    const float* fbi   = (const float*)d_in[10];
    const float* fwh   = (const float*)d_in[11];
    const float* fbh   = (const float*)d_in[12];
    const float* uaw   = (const float*)d_in[13];
    const float* uab   = (const float*)d_in[14];
    const float* ufw   = (const float*)d_in[15];
    const float* ufb   = (const float*)d_in[16];

    const int H  = in_sizes[2];
    const int O  = in_sizes[4];
    const int IN = in_sizes[1] / H;
    const int B  = in_sizes[0] / IN;
    const int nn = out_size / (B * O);
    int depth = 0;
    while (((2 << depth) - 1) < nn) depth++;

    float *H0p, *HAIp, *H2p, *PRp;
    unsigned char *WTCp, *WTCFp, *WUp;
    cudaGetSymbolAddress((void**)&H0p,  g_H0);
    cudaGetSymbolAddress((void**)&HAIp, g_HAI);
    cudaGetSymbolAddress((void**)&H2p,  g_H2);
    cudaGetSymbolAddress((void**)&PRp,  g_PR);
    cudaGetSymbolAddress((void**)&WTCp, g_WTC);
    cudaGetSymbolAddress((void**)&WTCFp, g_WTCF);
    cudaGetSymbolAddress((void**)&WUp,  g_WU);

    cudaFuncSetAttribute(node_tc,    cudaFuncAttributeMaxDynamicSharedMemorySize, SMEM_TCN);
    cudaFuncSetAttribute(combine_tc, cudaFuncAttributeMaxDynamicSharedMemorySize, SMEM_TCC);

    pack_wtc<<<(6464 + 127) / 128, 128>>>(awh, awi, fwh, fwi, ufw, uaw, h2o_w, WTCp, WTCFp, WUp);
    init_kernel<<<B / RB, NTHR>>>(z, z2h_w, z2h_b, H0p);

    EmitCtx P;
    P.h2o_b = h2o_b;
    P.abi = abi; P.abh = abh; P.fbi = fbi; P.fbh = fbh;
    P.uab = uab; P.ufb = ufb;
    P.WTC = WTCp; P.WTCF = WTCFp; P.WU = WUp;
    P.out = (float*)d_out;
    P.HAI = HAIp; P.H2 = H2p; P.PR = PRp;
    P.B = B; P.idx = 0;

    emit_node(P, 0, depth, H0p);
}

// round 16
// speedup vs baseline: 1.4553x; 1.1774x over previous
#include <cuda_runtime.h>
#include <cuda_fp16.h>
#include <cstdint>

#define Hdim 128
#define Odim 32
#define INdim 64
#define RB 8
#define NTHR 128
#define MAXB 16384
#define MAXLVL 6

__device__ float g_H0 [(size_t)MAXB * Hdim];
__device__ float g_HAI[(size_t)MAXLVL * MAXB * Hdim];
__device__ float g_H2 [(size_t)MAXLVL * MAXB * Hdim];
__device__ float g_PR [(size_t)(MAXLVL + 1) * MAXB * Odim];

__device__ __align__(1024) unsigned char g_WTC [184320]; // node: [5][576n][64B]
__device__ __align__(1024) unsigned char g_WTCF[163840]; // gru_f: [5][512n][64B]
__device__ __align__(1024) unsigned char g_WU  [65536];  // uf;ua: [8][128n][64B]

typedef unsigned long long u64;

__device__ __forceinline__ float sigmoidf_(float x) { return 1.0f / (1.0f + expf(-x)); }
__device__ __forceinline__ uint32_t smem_u32(const void* p) {
    uint32_t a;
    asm("{ .reg .u64 t; cvta.to.shared.u64 t, %1; cvt.u32.u64 %0, t; }" : "=r"(a) : "l"(p));
    return a;
}
__device__ __forceinline__ void ldsm4(uint32_t* r, uint32_t a) {
    asm volatile("ldmatrix.sync.aligned.m8n8.x4.shared.b16 {%0,%1,%2,%3}, [%4];"
        : "=r"(r[0]),"=r"(r[1]),"=r"(r[2]),"=r"(r[3]) : "r"(a));
}
__device__ __forceinline__ void ldsm2(uint32_t* r, uint32_t a) {
    asm volatile("ldmatrix.sync.aligned.m8n8.x2.shared.b16 {%0,%1}, [%2];"
        : "=r"(r[0]),"=r"(r[1]) : "r"(a));
}
__device__ __forceinline__ void mma16816(float* c, const uint32_t* a, const uint32_t* b) {
    asm volatile("mma.sync.aligned.m16n8k16.row.col.f32.f16.f16.f32 "
        "{%0,%1,%2,%3}, {%4,%5,%6,%7}, {%8,%9}, {%0,%1,%2,%3};"
        : "+f"(c[0]),"+f"(c[1]),"+f"(c[2]),"+f"(c[3])
        : "r"(a[0]),"r"(a[1]),"r"(a[2]),"r"(a[3]),"r"(b[0]),"r"(b[1]));
}
#define CPA16(d, s) asm volatile("cp.async.cg.shared.global [%0], [%1], 16;" :: "r"(d), "l"(s))
#define CPCOMMIT()  asm volatile("cp.async.commit_group;")
#define CPWAIT0()   asm volatile("cp.async.wait_group 0;")

__global__ void pack_wtc(const float* __restrict__ awh, const float* __restrict__ awi,
                         const float* __restrict__ fwh, const float* __restrict__ fwi,
                         const float* __restrict__ ufw, const float* __restrict__ uaw,
                         const float* __restrict__ h2o_w,
                         unsigned char* __restrict__ WTC, unsigned char* __restrict__ WTCF,
                         unsigned char* __restrict__ WU) {
    int id = blockIdx.x * blockDim.x + threadIdx.x;
    const float *wh, *wi;
    unsigned char* dst;
    int c, n, cs;
    if (id < 2880)      { c = id / 576;        n = id % 576;        wh = awh; wi = awi; dst = WTC;  cs = 36864; }
    else if (id < 5440) { c = (id-2880) / 512; n = (id-2880) % 512; wh = fwh; wi = fwi; dst = WTCF; cs = 32768; }
    else if (id < 6464) {
        int q = id - 5440; c = q >> 7; n = q & 127;
        const float* W = (c < 4) ? ufw : uaw;
        int kb = (c & 3) * 32;
        for (int s = 0; s < 4; s++) {
            __half seg[8];
            for (int i = 0; i < 8; i++)
                seg[i] = __float2half_rn(W[(size_t)(kb + s*8 + i)*128 + n]);
            size_t off = (size_t)c*8192 + (size_t)n*64 + (size_t)((s + (n>>1)) & 3)*16;
            *(float4*)(WU + off) = *(const float4*)seg;
        }
        return;
    } else return;
    for (int s = 0; s < 4; s++) {
        __half seg[8];
        for (int i = 0; i < 8; i++) {
            int gk = c*32 + s*8 + i;
            float w; __half hv;
            if (n < 512) {
                int gate = n >> 7, j = n & 127;
                if      (gate == 0) w = gk < 128 ? wh[(size_t)gk*128 + j] : wi[(size_t)(gk-128)*128 + j];
                else if (gate == 1) w = gk < 128 ? wh[16384 + (size_t)gk*128 + j] : wi[4096 + (size_t)(gk-128)*128 + j];
                else if (gate == 2) w = gk < 128 ? wh[32768 + (size_t)gk*128 + j] : 0.0f;
                else                w = gk < 128 ? 0.0f : wi[8192 + (size_t)(gk-128)*128 + j];
                hv = __float2half_rn(w);
            } else {
                int o = (n - 512) >> 1, pl = (n - 512) & 1;
                if (gk < 128) {
                    float f = h2o_w[(size_t)gk*32 + o];
                    __half hi = __float2half_rn(f);
                    hv = pl ? __float2half_rn(f - __half2float(hi)) : hi;
                } else hv = __float2half_rn(0.0f);
            }
            seg[i] = hv;
        }
        size_t off = (size_t)c*cs + (size_t)n*64 + (size_t)((s + (n>>1)) & 3)*16;
        *(float4*)(dst + off) = *(const float4*)seg;
    }
}

__global__ void __launch_bounds__(NTHR)
init_kernel(const float* __restrict__ z, const float* __restrict__ w,
            const float* __restrict__ b, float* __restrict__ hout) {
    __shared__ float zs[RB][INdim];
    const int j = threadIdx.x, row0 = blockIdx.x * RB;
    {
        const float4* src = reinterpret_cast<const float4*>(z + (size_t)row0 * INdim);
        float4* dst = reinterpret_cast<float4*>(&zs[0][0]);
        for (int i = j; i < RB * INdim / 4; i += NTHR) dst[i] = src[i];
    }
    __syncthreads();
    const float bb = b[j];
    float acc[RB];
#pragma unroll
    for (int i = 0; i < RB; i++) acc[i] = bb;
#pragma unroll 4
    for (int k = 0; k < INdim; k += 4) {
        float4 hv[RB];
#pragma unroll
        for (int i = 0; i < RB; i++) hv[i] = *reinterpret_cast<const float4*>(&zs[i][k]);
#pragma unroll
        for (int kk = 0; kk < 4; kk++) {
            float wv = w[(size_t)(k+kk)*Hdim + j];
#pragma unroll
            for (int i = 0; i < RB; i++) {
                float h = (kk==0)?hv[i].x:(kk==1)?hv[i].y:(kk==2)?hv[i].z:hv[i].w;
                acc[i] += h * wv;
            }
        }
    }
#pragma unroll
    for (int i = 0; i < RB; i++) hout[(size_t)(row0+i)*Hdim + j] = acc[i];
}

#define SM_AHI  0
#define SM_B    21504
#define SM_XN   168960
#define SMEM_TCN 201728
#define SMEM_TCC 185344
#define APITCH  336

__device__ __forceinline__ void load_h_tiles(unsigned char* smem, const float* __restrict__ h,
                                             int row0, int t) {
    for (int i = t; i < 2048; i += 512) {
        int row = i >> 5, k4 = i & 31;
        float4 v = ((const float4*)(h + (size_t)(row0+row)*Hdim))[k4];
        __half2 h01 = __floats2half2_rn(v.x, v.y);
        __half2 h23 = __floats2half2_rn(v.z, v.w);
        uint32_t o = (uint32_t)row*APITCH + k4*8;
        *(__half2*)(smem + SM_AHI + o)     = h01;
        *(__half2*)(smem + SM_AHI + o + 4) = h23;
    }
}
__device__ __forceinline__ void gate_epilogue(unsigned char* smem, float acc[2][8][4],
                                              const float* __restrict__ habs,
                                              const float* __restrict__ abi, const float* __restrict__ abh,
                                              int row0, int t, int wm, int wn, int lane,
                                              float hprime[16]) {
    float* exch = (float*)smem;
    const int row = t >> 3, j0 = (t & 7)*16;
    float rg[16], zg[16];
    if (wn < 4) {
        int gsel = wn >> 1;
#pragma unroll
        for (int tm = 0; tm < 2; tm++)
#pragma unroll
            for (int tn = 0; tn < 8; tn++) {
                int col = (wn & 1)*64 + tn*8 + 2*(lane & 3);
                int r1 = wm*32 + tm*16 + (lane >> 2);
                *(float2*)&exch[gsel*8448 + r1*132 + col]     = make_float2(acc[tm][tn][0], acc[tm][tn][1]);
                *(float2*)&exch[gsel*8448 + (r1+8)*132 + col] = make_float2(acc[tm][tn][2], acc[tm][tn][3]);
            }
    }
    __syncthreads();
#pragma unroll
    for (int b = 0; b < 4; b++) {
        int j = j0 + b*4;
        float4 vr = *(const float4*)&exch[row*132 + j];
        float4 vz = *(const float4*)&exch[8448 + row*132 + j];
        float4 bir = *(const float4*)&abi[j],     bhr = *(const float4*)&abh[j];
        float4 biz = *(const float4*)&abi[128+j], bhz = *(const float4*)&abh[128+j];
        const float *pr = (const float*)&vr, *pz = (const float*)&vz;
        const float *b1 = (const float*)&bir, *b2 = (const float*)&bhr;
        const float *b3 = (const float*)&biz, *b4 = (const float*)&bhz;
#pragma unroll
        for (int e = 0; e < 4; e++) {
            rg[b*4+e] = sigmoidf_(pr[e] + b1[e] + b2[e]);
            zg[b*4+e] = sigmoidf_(pz[e] + b3[e] + b4[e]);
        }
    }
    __syncthreads();
    if (wn >= 4) {
        int gsel = (wn - 4) >> 1;
#pragma unroll
        for (int tm = 0; tm < 2; tm++)
#pragma unroll
            for (int tn = 0; tn < 8; tn++) {
                int col = (wn & 1)*64 + tn*8 + 2*(lane & 3);
                int r1 = wm*32 + tm*16 + (lane >> 2);
                *(float2*)&exch[gsel*8448 + r1*132 + col]     = make_float2(acc[tm][tn][0], acc[tm][tn][1]);
                *(float2*)&exch[gsel*8448 + (r1+8)*132 + col] = make_float2(acc[tm][tn][2], acc[tm][tn][3]);
            }
    }
    __syncthreads();
#pragma unroll
    for (int b = 0; b < 4; b++) {
        int j = j0 + b*4;
        float4 vh = *(const float4*)&exch[row*132 + j];
        float4 vx = *(const float4*)&exch[8448 + row*132 + j];
        float4 bin = *(const float4*)&abi[256+j], bhn = *(const float4*)&abh[256+j];
        float4 hv = *(const float4*)(habs + (size_t)(row0+row)*Hdim + j);
        const float *ph = (const float*)&vh, *px = (const float*)&vx;
        const float *bn = (const float*)&bin, *hn = (const float*)&bhn;
        const float *pv = (const float*)&hv;
#pragma unroll
        for (int e = 0; e < 4; e++) {
            float nn = tanhf(px[e] + bn[e] + rg[b*4+e]*(ph[e] + hn[e]));
            hprime[b*4+e] = (1.0f - zg[b*4+e])*nn + zg[b*4+e]*pv[e];
        }
    }
}

// ======== node kernel: single-plane fp16 A, fused pred ========
__global__ void __launch_bounds__(512, 1)
node_tc(const float* __restrict__ h_a, const float* __restrict__ h2o_b,
        const unsigned char* __restrict__ WTC,
        const float* __restrict__ abi, const float* __restrict__ abh,
        float* __restrict__ pred_out, float* __restrict__ probs_out,
        float* __restrict__ h_out) {
    extern __shared__ __align__(128) unsigned char smem[];
    const uint32_t sb = smem_u32(smem);
    const int t = threadIdx.x, wid = t >> 5, lane = t & 31;
    const int row0 = blockIdx.x * 64;

    for (uint32_t off = (uint32_t)t*16; off < 147456u; off += 8192u)
        CPA16(sb + SM_B + off, WTC + off);
    CPCOMMIT();
    load_h_tiles(smem, h_a, row0, t);
    CPWAIT0();
    __syncthreads();

    const int wm = wid & 1, wn = wid >> 1;
    float acc[2][8][4], accp[2][4];
#pragma unroll
    for (int a = 0; a < 2; a++) {
#pragma unroll
        for (int i = 0; i < 8; i++)
#pragma unroll
            for (int q = 0; q < 4; q++) acc[a][i][q] = 0.0f;
#pragma unroll
        for (int q = 0; q < 4; q++) accp[a][q] = 0.0f;
    }
    const uint32_t abase = sb + SM_AHI + (uint32_t)(wm*32 + (lane & 15))*APITCH + (uint32_t)(lane >> 4)*16;
    const int roffB = ((lane >> 4) << 3) + (lane & 7);
    const int sgB   = (lane >> 3) & 1;
    const int prow  = 512 + wn*8 + (lane & 7);

    // phase A: chunks 0-3 (k=0..127), gates + pred
#pragma unroll
    for (int c = 0; c < 4; c++) {
        uint32_t bbuf = sb + SM_B + (uint32_t)c*36864u;
#pragma unroll
        for (int kk = 0; kk < 2; kk++) {
            uint32_t ah[2][4];
#pragma unroll
            for (int tm = 0; tm < 2; tm++)
                ldsm4(ah[tm], abase + (uint32_t)tm*16u*APITCH + (uint32_t)(c*32 + kk*16)*2);
#pragma unroll
            for (int tn2 = 0; tn2 < 4; tn2++) {
                int n = wn*64 + tn2*16 + roffB;
                uint32_t ba = bbuf + (uint32_t)n*64u + (uint32_t)(((2*kk + sgB + (n>>1)) & 3))*16u;
                uint32_t b[4];
                ldsm4(b, ba);
#pragma unroll
                for (int tm = 0; tm < 2; tm++) {
                    mma16816(acc[tm][tn2*2],   ah[tm], b);
                    mma16816(acc[tm][tn2*2+1], ah[tm], b+2);
                }
            }
            {
                uint32_t ba = bbuf + (uint32_t)prow*64u + (uint32_t)(((2*kk + sgB + (prow>>1)) & 3))*16u;
                uint32_t bp[2];
                ldsm2(bp, ba);
#pragma unroll
                for (int tm = 0; tm < 2; tm++)
                    mma16816(accp[tm], ah[tm], bp);
            }
        }
    }
    __syncthreads();

    // pred exchange into SM_XN
    {
        float* predx = (float*)(smem + SM_XN);
        const int o = 4*wn + (lane & 3);
#pragma unroll
        for (int tm = 0; tm < 2; tm++) {
            int r = wm*32 + tm*16 + (lane >> 2);
            predx[r*32 + o]     = accp[tm][0] + accp[tm][1];
            predx[(r+8)*32 + o] = accp[tm][2] + accp[tm][3];
        }
    }
    __syncthreads();

    if (t < 64) {   // streaming softmax
        const float* predx = (const float*)(smem + SM_XN);
        const int grow = row0 + t;
        float m = -1e30f;
#pragma unroll
        for (int q = 0; q < 8; q++) {
            float4 v = ((const float4*)(predx + t*32))[q];
            float4 bb = ((const float4*)h2o_b)[q];
            v.x += bb.x; v.y += bb.y; v.z += bb.z; v.w += bb.w;
            ((float4*)(pred_out + (size_t)grow*Odim))[q] = v;
            m = fmaxf(m, fmaxf(fmaxf(v.x, v.y), fmaxf(v.z, v.w)));
        }
        float ss = 0.0f;
#pragma unroll
        for (int q = 0; q < 8; q++) {
            float4 v = ((const float4*)(predx + t*32))[q];
            float4 bb = ((const float4*)h2o_b)[q];
            ss += expf(v.x + bb.x - m) + expf(v.y + bb.y - m)
                + expf(v.z + bb.z - m) + expf(v.w + bb.w - m);
        }
        float inv = 1.0f / ss;
#pragma unroll
        for (int q = 0; q < 8; q++) {
            float4 v = ((const float4*)(predx + t*32))[q];
            float4 bb = ((const float4*)h2o_b)[q];
            float4 p;
            p.x = expf(v.x + bb.x - m) * inv;
            p.y = expf(v.y + bb.y - m) * inv;
            p.z = expf(v.z + bb.z - m) * inv;
            p.w = expf(v.w + bb.w - m) * inv;
            ((float4*)(probs_out + (size_t)grow*Odim))[q] = p;
            __half2 h01 = __floats2half2_rn(p.x, p.y);
            __half2 h23 = __floats2half2_rn(p.z, p.w);
            uint32_t o = (uint32_t)t*APITCH + 256 + q*8;
            *(__half2*)(smem + SM_AHI + o)     = h01;
            *(__half2*)(smem + SM_AHI + o + 4) = h23;
        }
    }
    __syncthreads();

    {   // chunk 4 gate rows into SM_XN
        uint32_t dst = sb + SM_XN + (uint32_t)t*64u;
        const unsigned char* s0 = WTC + 4*36864 + (size_t)t*64;
#pragma unroll
        for (int q = 0; q < 4; q++) CPA16(dst + q*16, s0 + q*16);
        CPCOMMIT(); CPWAIT0();
    }
    __syncthreads();

    {   // phase B: chunk 4
        const int c = 4;
        uint32_t bbuf = sb + SM_XN;
#pragma unroll
        for (int kk = 0; kk < 2; kk++) {
            uint32_t ah[2][4];
#pragma unroll
            for (int tm = 0; tm < 2; tm++)
                ldsm4(ah[tm], abase + (uint32_t)tm*16u*APITCH + (uint32_t)(c*32 + kk*16)*2);
#pragma unroll
            for (int tn2 = 0; tn2 < 4; tn2++) {
                int n = wn*64 + tn2*16 + roffB;
                uint32_t ba = bbuf + (uint32_t)n*64u + (uint32_t)(((2*kk + sgB + (n>>1)) & 3))*16u;
                uint32_t b[4];
                ldsm4(b, ba);
#pragma unroll
                for (int tm = 0; tm < 2; tm++) {
                    mma16816(acc[tm][tn2*2],   ah[tm], b);
                    mma16816(acc[tm][tn2*2+1], ah[tm], b+2);
                }
            }
        }
    }
    __syncthreads();

    float hp[16];
    gate_epilogue(smem, acc, h_a, abi, abh, row0, t, wm, wn, lane, hp);
    {
        const int row = t >> 3, j0 = (t & 7)*16;
        float* po = h_out + (size_t)(row0+row)*Hdim + j0;
#pragma unroll
        for (int q = 0; q < 4; q++)
            *(float4*)(po + q*4) = make_float4(hp[q*4], hp[q*4+1], hp[q*4+2], hp[q*4+3]);
    }
}

// ======== combine kernel ========
__global__ void __launch_bounds__(512, 1)
combine_tc(const float* __restrict__ probs_fc,
           const float* __restrict__ h_ai, const float* __restrict__ h_a,
           const unsigned char* __restrict__ WTCF,
           const float* __restrict__ fbi, const float* __restrict__ fbh,
           const unsigned char* __restrict__ WU,
           const float* __restrict__ ufb, const float* __restrict__ uab,
           float* __restrict__ h2_out) {
    extern __shared__ __align__(128) unsigned char smem[];
    const uint32_t sb = smem_u32(smem);
    const int t = threadIdx.x, lane = t & 31, wid = t >> 5;
    const int wm = wid & 1, wn = wid >> 1;
    const int row0 = blockIdx.x * 64;

    for (uint32_t off = (uint32_t)t*16; off < 163840u; off += 8192u)
        CPA16(sb + SM_B + off, WTCF + off);
    CPCOMMIT();
    load_h_tiles(smem, h_ai, row0, t);
#pragma unroll
    for (int q = 0; q < 4; q++) {
        int idx = t*4 + q, row = idx >> 5, c = idx & 31;
        float p = probs_fc[(size_t)(row0+row)*Odim + c];
        uint32_t o = (uint32_t)row*APITCH + 256 + 2*c;
        *(__half*)(smem + SM_AHI + o) = __float2half_rn(p);
    }
    CPWAIT0();
    __syncthreads();

    float acc[2][8][4];
#pragma unroll
    for (int a = 0; a < 2; a++)
#pragma unroll
        for (int i = 0; i < 8; i++)
#pragma unroll
            for (int q = 0; q < 4; q++) acc[a][i][q] = 0.0f;

    const uint32_t abase = sb + SM_AHI + (uint32_t)(wm*32 + (lane & 15))*APITCH + (uint32_t)(lane >> 4)*16;
    const int roffB = ((lane >> 4) << 3) + (lane & 7);
    const int sgB   = (lane >> 3) & 1;
#pragma unroll
    for (int c = 0; c < 5; c++) {
        uint32_t bbuf = sb + SM_B + (uint32_t)c*32768u;
#pragma unroll
        for (int kk = 0; kk < 2; kk++) {
            uint32_t ah[2][4];
#pragma unroll
            for (int tm = 0; tm < 2; tm++)
                ldsm4(ah[tm], abase + (uint32_t)tm*16u*APITCH + (uint32_t)(c*32 + kk*16)*2);
#pragma unroll
            for (int tn2 = 0; tn2 < 4; tn2++) {
                int n = wn*64 + tn2*16 + roffB;
                uint32_t ba = bbuf + (uint32_t)n*64u + (uint32_t)(((2*kk + sgB + (n>>1)) & 3))*16u;
                uint32_t b[4];
                ldsm4(b, ba);
#pragma unroll
                for (int tm = 0; tm < 2; tm++) {
                    mma16816(acc[tm][tn2*2],   ah[tm], b);
                    mma16816(acc[tm][tn2*2+1], ah[tm], b+2);
                }
            }
        }
    }
    __syncthreads();
    float hf[16];
    gate_epilogue(smem, acc, h_ai, fbi, fbh, row0, t, wm, wn, lane, hf);
    __syncthreads();

    {   // hf -> A tiles
        const int row = t >> 3, j0 = (t & 7)*16;
#pragma unroll
        for (int q = 0; q < 8; q++) {
            __half2 hh = __floats2half2_rn(hf[q*2], hf[q*2+1]);
            uint32_t o = (uint32_t)row*APITCH + (j0 + q*2)*2;
            *(__half2*)(smem + SM_AHI + o) = hh;
        }
    }
    __syncthreads();

    float acc2[2][2][4];
#pragma unroll
    for (int a = 0; a < 2; a++)
#pragma unroll
        for (int i = 0; i < 2; i++)
#pragma unroll
            for (int q = 0; q < 4; q++) acc2[a][i][q] = 0.0f;

    for (int ph = 0; ph < 2; ph++) {
        if (ph == 1) {
            __syncthreads();
            load_h_tiles(smem, h_a, row0, t);
        }
        {
            if (t < 128) {
#pragma unroll
                for (int c2 = 0; c2 < 4; c2++) {
                    uint32_t dst = sb + SM_B + (uint32_t)c2*8192u + (uint32_t)t*64u;
                    const unsigned char* s0 = WU + (size_t)(ph*4 + c2)*8192 + (size_t)t*64;
#pragma unroll
                    for (int q = 0; q < 4; q++) CPA16(dst + q*16, s0 + q*16);
                }
            }
            CPCOMMIT(); CPWAIT0();
            __syncthreads();
        }
#pragma unroll
        for (int c2 = 0; c2 < 4; c2++) {
#pragma unroll
            for (int kk = 0; kk < 2; kk++) {
                uint32_t ah[2][4];
#pragma unroll
                for (int tm = 0; tm < 2; tm++)
                    ldsm4(ah[tm], abase + (uint32_t)tm*16u*APITCH + (uint32_t)(c2*32 + kk*16)*2);
                int n = wn*16 + roffB;
                uint32_t ba = sb + SM_B + (uint32_t)c2*8192u + (uint32_t)n*64u
                            + (uint32_t)(((2*kk + sgB + (n>>1)) & 3))*16u;
                uint32_t b[4];
                ldsm4(b, ba);
#pragma unroll
                for (int tm = 0; tm < 2; tm++) {
                    mma16816(acc2[tm][0], ah[tm], b);
                    mma16816(acc2[tm][1], ah[tm], b+2);
                }
            }
        }
        __syncthreads();
    }

    {
        float* exch = (float*)smem;
#pragma unroll
        for (int tm = 0; tm < 2; tm++)
#pragma unroll
            for (int tn = 0; tn < 2; tn++) {
                int col = wn*16 + tn*8 + 2*(lane & 3);
                int r1 = wm*32 + tm*16 + (lane >> 2);
                *(float2*)&exch[r1*132 + col]     = make_float2(acc2[tm][tn][0], acc2[tm][tn][1]);
                *(float2*)&exch[(r1+8)*132 + col] = make_float2(acc2[tm][tn][2], acc2[tm][tn][3]);
            }
        __syncthreads();
        const int row = t >> 3, j0 = (t & 7)*16;
        float* po = h2_out + (size_t)(row0+row)*Hdim + j0;
#pragma unroll
        for (int b = 0; b < 4; b++) {
            int j = j0 + b*4;
            float4 v = *(const float4*)&exch[row*132 + j];
            float4 b1 = *(const float4*)&ufb[j], b2 = *(const float4*)&uab[j];
            float4 out;
            out.x = tanhf(v.x + b1.x + b2.x);
            out.y = tanhf(v.y + b1.y + b2.y);
            out.z = tanhf(v.z + b1.z + b2.z);
            out.w = tanhf(v.w + b1.w + b2.w);
            *(float4*)(po + b*4) = out;
        }
    }
}

// ======== host orchestration ========
struct EmitCtx {
    const float *h2o_b, *abi, *abh, *fbi, *fbh, *uab, *ufb;
    const unsigned char *WTC, *WTCF, *WU;
    float *out, *HAI, *H2, *PR;
    int B, idx;
};

static void emit_node(EmitCtx& P, int lvl, int d, const float* h_in) {
    float* probs = P.PR  + (size_t)lvl * P.B * Odim;
    float* h_ai  = P.HAI + (size_t)lvl * P.B * Hdim;
    node_tc<<<P.B / 64, 512, SMEM_TCN>>>(h_in, P.h2o_b, P.WTC, P.abi, P.abh,
                                         P.out + (size_t)P.idx * P.B * Odim, probs, h_ai);
    P.idx++;
    if (d > 0) {
        emit_node(P, lvl + 1, d - 1, h_ai);
        float* h2 = P.H2 + (size_t)lvl * P.B * Hdim;
        combine_tc<<<P.B / 64, 512, SMEM_TCC>>>(P.PR + (size_t)(lvl+1) * P.B * Odim,
                                                h_ai, h_in, P.WTCF, P.fbi, P.fbh,
                                                P.WU, P.ufb, P.uab, h2);
        emit_node(P, lvl + 1, d - 1, h2);
    }
}

extern "C" void kernel_launch(void* const* d_in, const int* in_sizes, int n_in,
                              void* d_out, int out_size) {
    const float* z     = (const float*)d_in[0];
    const float* z2h_w = (const float*)d_in[1];
    const float* z2h_b = (const float*)d_in[2];
    const float* h2o_w = (const float*)d_in[3];
    const float* h2o_b = (const float*)d_in[4];
    const float* awi   = (const float*)d_in[5];
    const float* abi   = (const float*)d_in[6];
    const float* awh   = (const float*)d_in[7];
    const float* abh   = (const float*)d_in[8];
    const float* fwi   = (const float*)d_in[9];
    const float* fbi   = (const float*)d_in[10];
    const float* fwh   = (const float*)d_in[11];
    const float* fbh   = (const float*)d_in[12];
    const float* uaw   = (const float*)d_in[13];
    const float* uab   = (const float*)d_in[14];
    const float* ufw   = (const float*)d_in[15];
    const float* ufb   = (const float*)d_in[16];

    const int H  = in_sizes[2];
    const int O  = in_sizes[4];
    const int IN = in_sizes[1] / H;
    const int B  = in_sizes[0] / IN;
    const int nn = out_size / (B * O);
    int depth = 0;
    while (((2 << depth) - 1) < nn) depth++;

    float *H0p, *HAIp, *H2p, *PRp;
    unsigned char *WTCp, *WTCFp, *WUp;
    cudaGetSymbolAddress((void**)&H0p,  g_H0);
    cudaGetSymbolAddress((void**)&HAIp, g_HAI);
    cudaGetSymbolAddress((void**)&H2p,  g_H2);
    cudaGetSymbolAddress((void**)&PRp,  g_PR);
    cudaGetSymbolAddress((void**)&WTCp, g_WTC);
    cudaGetSymbolAddress((void**)&WTCFp, g_WTCF);
    cudaGetSymbolAddress((void**)&WUp,  g_WU);

    cudaFuncSetAttribute(node_tc,    cudaFuncAttributeMaxDynamicSharedMemorySize, SMEM_TCN);
    cudaFuncSetAttribute(combine_tc, cudaFuncAttributeMaxDynamicSharedMemorySize, SMEM_TCC);

    pack_wtc<<<(6464 + 127) / 128, 128>>>(awh, awi, fwh, fwi, ufw, uaw, h2o_w, WTCp, WTCFp, WUp);
    init_kernel<<<B / RB, NTHR>>>(z, z2h_w, z2h_b, H0p);

    EmitCtx P;
    P.h2o_b = h2o_b;
    P.abi = abi; P.abh = abh; P.fbi = fbi; P.fbh = fbh;
    P.uab = uab; P.ufb = ufb;
    P.WTC = WTCp; P.WTCF = WTCFp; P.WU = WUp;
    P.out = (float*)d_out;
    P.HAI = HAIp; P.H2 = H2p; P.PR = PRp;
    P.B = B; P.idx = 0;

    emit_node(P, 0, depth, H0p);
}

// round 17
// speedup vs baseline: 1.5110x; 1.0383x over previous
#include <cuda_runtime.h>
#include <cuda_fp16.h>
#include <cstdint>

#define Hdim 128
#define Odim 32
#define INdim 64
#define RB 8
#define NTHR 128
#define MAXB 16384
#define MAXLVL 6

__device__ float g_H0 [(size_t)MAXB * Hdim];
__device__ float g_HAI[(size_t)MAXLVL * MAXB * Hdim];
__device__ float g_H2 [(size_t)MAXLVL * MAXB * Hdim];
__device__ float g_PR [(size_t)(MAXLVL + 1) * MAXB * Odim];

__device__ __align__(1024) unsigned char g_WTC [184320]; // node: [5][576n][64B]
__device__ __align__(1024) unsigned char g_WTCF[163840]; // gru_f: [5][512n][64B]
__device__ __align__(1024) unsigned char g_WU  [65536];  // uf;ua: [8][128n][64B]

__device__ __forceinline__ float sigmoidf_(float x) { return 1.0f / (1.0f + expf(-x)); }
__device__ __forceinline__ uint32_t smem_u32(const void* p) {
    uint32_t a;
    asm("{ .reg .u64 t; cvta.to.shared.u64 t, %1; cvt.u32.u64 %0, t; }" : "=r"(a) : "l"(p));
    return a;
}
__device__ __forceinline__ void ldsm4(uint32_t* r, uint32_t a) {
    asm volatile("ldmatrix.sync.aligned.m8n8.x4.shared.b16 {%0,%1,%2,%3}, [%4];"
        : "=r"(r[0]),"=r"(r[1]),"=r"(r[2]),"=r"(r[3]) : "r"(a));
}
__device__ __forceinline__ void ldsm2(uint32_t* r, uint32_t a) {
    asm volatile("ldmatrix.sync.aligned.m8n8.x2.shared.b16 {%0,%1}, [%2];"
        : "=r"(r[0]),"=r"(r[1]) : "r"(a));
}
__device__ __forceinline__ void mma16816(float* c, const uint32_t* a, const uint32_t* b) {
    asm volatile("mma.sync.aligned.m16n8k16.row.col.f32.f16.f16.f32 "
        "{%0,%1,%2,%3}, {%4,%5,%6,%7}, {%8,%9}, {%0,%1,%2,%3};"
        : "+f"(c[0]),"+f"(c[1]),"+f"(c[2]),"+f"(c[3])
        : "r"(a[0]),"r"(a[1]),"r"(a[2]),"r"(a[3]),"r"(b[0]),"r"(b[1]));
}
#define CPA16(d, s) asm volatile("cp.async.cg.shared.global [%0], [%1], 16;" :: "r"(d), "l"(s))
#define CPCOMMIT()  asm volatile("cp.async.commit_group;")
#define CPWAIT1()   asm volatile("cp.async.wait_group 1;")
#define CPWAIT0()   asm volatile("cp.async.wait_group 0;")

__global__ void pack_wtc(const float* __restrict__ awh, const float* __restrict__ awi,
                         const float* __restrict__ fwh, const float* __restrict__ fwi,
                         const float* __restrict__ ufw, const float* __restrict__ uaw,
                         const float* __restrict__ h2o_w,
                         unsigned char* __restrict__ WTC, unsigned char* __restrict__ WTCF,
                         unsigned char* __restrict__ WU) {
    int id = blockIdx.x * blockDim.x + threadIdx.x;
    const float *wh, *wi;
    unsigned char* dst;
    int c, n, cs;
    if (id < 2880)      { c = id / 576;        n = id % 576;        wh = awh; wi = awi; dst = WTC;  cs = 36864; }
    else if (id < 5440) { c = (id-2880) / 512; n = (id-2880) % 512; wh = fwh; wi = fwi; dst = WTCF; cs = 32768; }
    else if (id < 6464) {
        int q = id - 5440; c = q >> 7; n = q & 127;
        const float* W = (c < 4) ? ufw : uaw;
        int kb = (c & 3) * 32;
        for (int s = 0; s < 4; s++) {
            __half seg[8];
            for (int i = 0; i < 8; i++)
                seg[i] = __float2half_rn(W[(size_t)(kb + s*8 + i)*128 + n]);
            size_t off = (size_t)c*8192 + (size_t)n*64 + (size_t)((s + (n>>1)) & 3)*16;
            *(float4*)(WU + off) = *(const float4*)seg;
        }
        return;
    } else return;
    for (int s = 0; s < 4; s++) {
        __half seg[8];
        for (int i = 0; i < 8; i++) {
            int gk = c*32 + s*8 + i;
            float w; __half hv;
            if (n < 512) {
                int gate = n >> 7, j = n & 127;
                if      (gate == 0) w = gk < 128 ? wh[(size_t)gk*128 + j] : wi[(size_t)(gk-128)*128 + j];
                else if (gate == 1) w = gk < 128 ? wh[16384 + (size_t)gk*128 + j] : wi[4096 + (size_t)(gk-128)*128 + j];
                else if (gate == 2) w = gk < 128 ? wh[32768 + (size_t)gk*128 + j] : 0.0f;
                else                w = gk < 128 ? 0.0f : wi[8192 + (size_t)(gk-128)*128 + j];
                hv = __float2half_rn(w);
            } else {
                int o = (n - 512) >> 1, pl = (n - 512) & 1;
                if (gk < 128) {
                    float f = h2o_w[(size_t)gk*32 + o];
                    __half hi = __float2half_rn(f);
                    hv = pl ? __float2half_rn(f - __half2float(hi)) : hi;
                } else hv = __float2half_rn(0.0f);
            }
            seg[i] = hv;
        }
        size_t off = (size_t)c*cs + (size_t)n*64 + (size_t)((s + (n>>1)) & 3)*16;
        *(float4*)(dst + off) = *(const float4*)seg;
    }
}

__global__ void __launch_bounds__(NTHR)
init_kernel(const float* __restrict__ z, const float* __restrict__ w,
            const float* __restrict__ b, float* __restrict__ hout) {
    __shared__ float zs[RB][INdim];
    const int j = threadIdx.x, row0 = blockIdx.x * RB;
    {
        const float4* src = reinterpret_cast<const float4*>(z + (size_t)row0 * INdim);
        float4* dst = reinterpret_cast<float4*>(&zs[0][0]);
        for (int i = j; i < RB * INdim / 4; i += NTHR) dst[i] = src[i];
    }
    __syncthreads();
    const float bb = b[j];
    float acc[RB];
#pragma unroll
    for (int i = 0; i < RB; i++) acc[i] = bb;
#pragma unroll 4
    for (int k = 0; k < INdim; k += 4) {
        float4 hv[RB];
#pragma unroll
        for (int i = 0; i < RB; i++) hv[i] = *reinterpret_cast<const float4*>(&zs[i][k]);
#pragma unroll
        for (int kk = 0; kk < 4; kk++) {
            float wv = w[(size_t)(k+kk)*Hdim + j];
#pragma unroll
            for (int i = 0; i < RB; i++) {
                float h = (kk==0)?hv[i].x:(kk==1)?hv[i].y:(kk==2)?hv[i].z:hv[i].w;
                acc[i] += h * wv;
            }
        }
    }
#pragma unroll
    for (int i = 0; i < RB; i++) hout[(size_t)(row0+i)*Hdim + j] = acc[i];
}

#define SM_W    21504
#define SM_X    168960
#define SM_PX   205824
#define SMEM_TC 214016
#define APITCH  336

__device__ __forceinline__ void load_h_tiles(unsigned char* smem, const float* __restrict__ h,
                                             int row0, int t) {
    for (int i = t; i < 2048; i += 512) {
        int row = i >> 5, k4 = i & 31;
        float4 v = ((const float4*)(h + (size_t)(row0+row)*Hdim))[k4];
        __half2 h01 = __floats2half2_rn(v.x, v.y);
        __half2 h23 = __floats2half2_rn(v.z, v.w);
        uint32_t o = (uint32_t)row*APITCH + k4*8;
        *(__half2*)(smem + o)     = h01;
        *(__half2*)(smem + o + 4) = h23;
    }
}
// unified GRU epilogue; hv[16] thread-local (same (row,j) mapping)
__device__ __forceinline__ void gate_epilogue(unsigned char* smem, float acc[2][8][4],
                                              const float hv[16],
                                              const float* __restrict__ bi, const float* __restrict__ bh,
                                              int t, int wm, int wn, int lane, float out16[16]) {
    float* exch = (float*)smem;
    const int row = t >> 3, j0 = (t & 7)*16;
    float rg[16], zg[16];
    if (wn < 4) {
        int gsel = wn >> 1;
#pragma unroll
        for (int tm = 0; tm < 2; tm++)
#pragma unroll
            for (int tn = 0; tn < 8; tn++) {
                int col = (wn & 1)*64 + tn*8 + 2*(lane & 3);
                int r1 = wm*32 + tm*16 + (lane >> 2);
                *(float2*)&exch[gsel*8448 + r1*132 + col]     = make_float2(acc[tm][tn][0], acc[tm][tn][1]);
                *(float2*)&exch[gsel*8448 + (r1+8)*132 + col] = make_float2(acc[tm][tn][2], acc[tm][tn][3]);
            }
    }
    __syncthreads();
#pragma unroll
    for (int b = 0; b < 4; b++) {
        int j = j0 + b*4;
        float4 vr = *(const float4*)&exch[row*132 + j];
        float4 vz = *(const float4*)&exch[8448 + row*132 + j];
        float4 bir = *(const float4*)&bi[j],     bhr = *(const float4*)&bh[j];
        float4 biz = *(const float4*)&bi[128+j], bhz = *(const float4*)&bh[128+j];
        const float *pr = (const float*)&vr, *pz = (const float*)&vz;
        const float *b1 = (const float*)&bir, *b2 = (const float*)&bhr;
        const float *b3 = (const float*)&biz, *b4 = (const float*)&bhz;
#pragma unroll
        for (int e = 0; e < 4; e++) {
            rg[b*4+e] = sigmoidf_(pr[e] + b1[e] + b2[e]);
            zg[b*4+e] = sigmoidf_(pz[e] + b3[e] + b4[e]);
        }
    }
    __syncthreads();
    if (wn >= 4) {
        int gsel = (wn - 4) >> 1;
#pragma unroll
        for (int tm = 0; tm < 2; tm++)
#pragma unroll
            for (int tn = 0; tn < 8; tn++) {
                int col = (wn & 1)*64 + tn*8 + 2*(lane & 3);
                int r1 = wm*32 + tm*16 + (lane >> 2);
                *(float2*)&exch[gsel*8448 + r1*132 + col]     = make_float2(acc[tm][tn][0], acc[tm][tn][1]);
                *(float2*)&exch[gsel*8448 + (r1+8)*132 + col] = make_float2(acc[tm][tn][2], acc[tm][tn][3]);
            }
    }
    __syncthreads();
#pragma unroll
    for (int b = 0; b < 4; b++) {
        int j = j0 + b*4;
        float4 vh = *(const float4*)&exch[row*132 + j];
        float4 vx = *(const float4*)&exch[8448 + row*132 + j];
        float4 bin = *(const float4*)&bi[256+j], bhn = *(const float4*)&bh[256+j];
        const float *ph = (const float*)&vh, *px = (const float*)&vx;
        const float *bn = (const float*)&bin, *hn = (const float*)&bhn;
#pragma unroll
        for (int e = 0; e < 4; e++) {
            float nn = tanhf(px[e] + bn[e] + rg[b*4+e]*(ph[e] + hn[e]));
            out16[b*4+e] = (1.0f - zg[b*4+e])*nn + zg[b*4+e]*hv[b*4+e];
        }
    }
}
__device__ __forceinline__ void load_hv16(const float* __restrict__ h, int row0, int t, float hv[16]) {
    const int row = t >> 3, j0 = (t & 7)*16;
#pragma unroll
    for (int q = 0; q < 4; q++) {
        float4 v = *(const float4*)(h + (size_t)(row0+row)*Hdim + j0 + q*4);
        hv[q*4] = v.x; hv[q*4+1] = v.y; hv[q*4+2] = v.z; hv[q*4+3] = v.w;
    }
}
// node gate phase A (chunks 0-3 at SM_W stride 36864) + pred
__device__ __forceinline__ void node_gatesA(uint32_t sb, int wm, int wn, int lane,
                                            float acc[2][8][4], float accp[2][4]) {
    const uint32_t abase = sb + (uint32_t)(wm*32 + (lane & 15))*APITCH + (uint32_t)(lane >> 4)*16;
    const int roffB = ((lane >> 4) << 3) + (lane & 7);
    const int sgB   = (lane >> 3) & 1;
    const int prow  = 512 + wn*8 + (lane & 7);
#pragma unroll
    for (int c = 0; c < 4; c++) {
        uint32_t bbuf = sb + SM_W + (uint32_t)c*36864u;
#pragma unroll
        for (int kk = 0; kk < 2; kk++) {
            uint32_t ah[2][4];
#pragma unroll
            for (int tm = 0; tm < 2; tm++)
                ldsm4(ah[tm], abase + (uint32_t)tm*16u*APITCH + (uint32_t)(c*32 + kk*16)*2);
#pragma unroll
            for (int tn2 = 0; tn2 < 4; tn2++) {
                int n = wn*64 + tn2*16 + roffB;
                uint32_t ba = bbuf + (uint32_t)n*64u + (uint32_t)(((2*kk + sgB + (n>>1)) & 3))*16u;
                uint32_t b[4];
                ldsm4(b, ba);
#pragma unroll
                for (int tm = 0; tm < 2; tm++) {
                    mma16816(acc[tm][tn2*2],   ah[tm], b);
                    mma16816(acc[tm][tn2*2+1], ah[tm], b+2);
                }
            }
            {
                uint32_t ba = bbuf + (uint32_t)prow*64u + (uint32_t)(((2*kk + sgB + (prow>>1)) & 3))*16u;
                uint32_t bp[2];
                ldsm2(bp, ba);
#pragma unroll
                for (int tm = 0; tm < 2; tm++)
                    mma16816(accp[tm], ah[tm], bp);
            }
        }
    }
}
// node gate phase B (chunk 4 at SM_X)
__device__ __forceinline__ void node_gatesB(uint32_t sb, int wm, int wn, int lane,
                                            float acc[2][8][4]) {
    const uint32_t abase = sb + (uint32_t)(wm*32 + (lane & 15))*APITCH + (uint32_t)(lane >> 4)*16;
    const int roffB = ((lane >> 4) << 3) + (lane & 7);
    const int sgB   = (lane >> 3) & 1;
#pragma unroll
    for (int kk = 0; kk < 2; kk++) {
        uint32_t ah[2][4];
#pragma unroll
        for (int tm = 0; tm < 2; tm++)
            ldsm4(ah[tm], abase + (uint32_t)tm*16u*APITCH + (uint32_t)(128 + kk*16)*2);
#pragma unroll
        for (int tn2 = 0; tn2 < 4; tn2++) {
            int n = wn*64 + tn2*16 + roffB;
            uint32_t ba = sb + SM_X + (uint32_t)n*64u + (uint32_t)(((2*kk + sgB + (n>>1)) & 3))*16u;
            uint32_t b[4];
            ldsm4(b, ba);
#pragma unroll
            for (int tm = 0; tm < 2; tm++) {
                mma16816(acc[tm][tn2*2],   ah[tm], b);
                mma16816(acc[tm][tn2*2+1], ah[tm], b+2);
            }
        }
    }
}
// pred exchange + softmax + probs -> A cols
__device__ __forceinline__ void pred_softmax(unsigned char* smem, int t, int wm, int wn, int lane,
                                             float accp[2][4], const float* __restrict__ h2o_b,
                                             float* __restrict__ pred_out, float* __restrict__ probs_out,
                                             int row0) {
    {
        float* predx = (float*)(smem + SM_PX);
        const int o = 4*wn + (lane & 3);
#pragma unroll
        for (int tm = 0; tm < 2; tm++) {
            int r = wm*32 + tm*16 + (lane >> 2);
            predx[r*32 + o]     = accp[tm][0] + accp[tm][1];
            predx[(r+8)*32 + o] = accp[tm][2] + accp[tm][3];
        }
    }
    __syncthreads();
    if (t < 64) {
        const float* predx = (const float*)(smem + SM_PX);
        const int grow = row0 + t;
        float m = -1e30f;
#pragma unroll
        for (int q = 0; q < 8; q++) {
            float4 v = ((const float4*)(predx + t*32))[q];
            float4 bb = ((const float4*)h2o_b)[q];
            v.x += bb.x; v.y += bb.y; v.z += bb.z; v.w += bb.w;
            ((float4*)(pred_out + (size_t)grow*Odim))[q] = v;
            m = fmaxf(m, fmaxf(fmaxf(v.x, v.y), fmaxf(v.z, v.w)));
        }
        float ss = 0.0f;
#pragma unroll
        for (int q = 0; q < 8; q++) {
            float4 v = ((const float4*)(predx + t*32))[q];
            float4 bb = ((const float4*)h2o_b)[q];
            ss += expf(v.x + bb.x - m) + expf(v.y + bb.y - m)
                + expf(v.z + bb.z - m) + expf(v.w + bb.w - m);
        }
        float inv = 1.0f / ss;
#pragma unroll
        for (int q = 0; q < 8; q++) {
            float4 v = ((const float4*)(predx + t*32))[q];
            float4 bb = ((const float4*)h2o_b)[q];
            float4 p;
            p.x = expf(v.x + bb.x - m) * inv;
            p.y = expf(v.y + bb.y - m) * inv;
            p.z = expf(v.z + bb.z - m) * inv;
            p.w = expf(v.w + bb.w - m) * inv;
            ((float4*)(probs_out + (size_t)grow*Odim))[q] = p;
            __half2 h01 = __floats2half2_rn(p.x, p.y);
            __half2 h23 = __floats2half2_rn(p.z, p.w);
            uint32_t o = (uint32_t)t*APITCH + 256 + q*8;
            *(__half2*)(smem + o)     = h01;
            *(__half2*)(smem + o + 4) = h23;
        }
    }
    __syncthreads();
}

// ======== standalone node kernel (all-5 resident) ========
__global__ void __launch_bounds__(512, 1)
node_tc(const float* __restrict__ h_a, const float* __restrict__ h2o_b,
        const unsigned char* __restrict__ WTC,
        const float* __restrict__ abi, const float* __restrict__ abh,
        float* __restrict__ pred_out, float* __restrict__ probs_out,
        float* __restrict__ h_out) {
    extern __shared__ __align__(128) unsigned char smem[];
    const uint32_t sb = smem_u32(smem);
    const int t = threadIdx.x, wid = t >> 5, lane = t & 31;
    const int wm = wid & 1, wn = wid >> 1;
    const int row0 = blockIdx.x * 64;

    for (uint32_t off = (uint32_t)t*16; off < 184320u; off += 8192u)
        CPA16(sb + SM_W + off, WTC + off);
    CPCOMMIT();
    load_h_tiles(smem, h_a, row0, t);
    CPWAIT0();
    __syncthreads();

    float acc[2][8][4], accp[2][4];
#pragma unroll
    for (int a = 0; a < 2; a++) {
#pragma unroll
        for (int i = 0; i < 8; i++)
#pragma unroll
            for (int q = 0; q < 4; q++) acc[a][i][q] = 0.0f;
#pragma unroll
        for (int q = 0; q < 4; q++) accp[a][q] = 0.0f;
    }
    node_gatesA(sb, wm, wn, lane, acc, accp);
    __syncthreads();
    pred_softmax(smem, t, wm, wn, lane, accp, h2o_b, pred_out, probs_out, row0);
    node_gatesB(sb, wm, wn, lane, acc);
    __syncthreads();

    float hv[16], hp[16];
    load_hv16(h_a, row0, t, hv);
    gate_epilogue(smem, acc, hv, abi, abh, t, wm, wn, lane, hp);
    {
        const int row = t >> 3, j0 = (t & 7)*16;
        float* po = h_out + (size_t)(row0+row)*Hdim + j0;
#pragma unroll
        for (int q = 0; q < 4; q++)
            *(float4*)(po + q*4) = make_float4(hp[q*4], hp[q*4+1], hp[q*4+2], hp[q*4+3]);
    }
}

// ======== fused combine + right-child node ========
__global__ void __launch_bounds__(512, 1)
fused_tc(const float* __restrict__ probs_fc,
         const float* __restrict__ h_ai, const float* __restrict__ h_a,
         const unsigned char* __restrict__ WTCF,
         const float* __restrict__ fbi, const float* __restrict__ fbh,
         const unsigned char* __restrict__ WU,
         const float* __restrict__ ufb, const float* __restrict__ uab,
         const unsigned char* __restrict__ WTC, const float* __restrict__ h2o_b,
         const float* __restrict__ abi, const float* __restrict__ abh,
         float* __restrict__ h2_out, float* __restrict__ pred_out,
         float* __restrict__ probs_out, float* __restrict__ h_out) {
    extern __shared__ __align__(128) unsigned char smem[];
    const uint32_t sb = smem_u32(smem);
    const int t = threadIdx.x, wid = t >> 5, lane = t & 31;
    const int wm = wid & 1, wn = wid >> 1;
    const int row0 = blockIdx.x * 64;

    for (uint32_t off = (uint32_t)t*16; off < 163840u; off += 8192u)
        CPA16(sb + SM_W + off, WTCF + off);
    CPCOMMIT();
    load_h_tiles(smem, h_ai, row0, t);
#pragma unroll
    for (int q = 0; q < 4; q++) {
        int idx = t*4 + q, row = idx >> 5, c = idx & 31;
        float p = probs_fc[(size_t)(row0+row)*Odim + c];
        uint32_t o = (uint32_t)row*APITCH + 256 + 2*c;
        *(__half*)(smem + o) = __float2half_rn(p);
    }
    CPWAIT0();
    __syncthreads();

    // combine gates (WTCF, chunk stride 32768)
    float acc[2][8][4];
#pragma unroll
    for (int a = 0; a < 2; a++)
#pragma unroll
        for (int i = 0; i < 8; i++)
#pragma unroll
            for (int q = 0; q < 4; q++) acc[a][i][q] = 0.0f;
    const uint32_t abase = sb + (uint32_t)(wm*32 + (lane & 15))*APITCH + (uint32_t)(lane >> 4)*16;
    const int roffB = ((lane >> 4) << 3) + (lane & 7);
    const int sgB   = (lane >> 3) & 1;
#pragma unroll
    for (int c = 0; c < 5; c++) {
        uint32_t bbuf = sb + SM_W + (uint32_t)c*32768u;
#pragma unroll
        for (int kk = 0; kk < 2; kk++) {
            uint32_t ah[2][4];
#pragma unroll
            for (int tm = 0; tm < 2; tm++)
                ldsm4(ah[tm], abase + (uint32_t)tm*16u*APITCH + (uint32_t)(c*32 + kk*16)*2);
#pragma unroll
            for (int tn2 = 0; tn2 < 4; tn2++) {
                int n = wn*64 + tn2*16 + roffB;
                uint32_t ba = bbuf + (uint32_t)n*64u + (uint32_t)(((2*kk + sgB + (n>>1)) & 3))*16u;
                uint32_t b[4];
                ldsm4(b, ba);
#pragma unroll
                for (int tm = 0; tm < 2; tm++) {
                    mma16816(acc[tm][tn2*2],   ah[tm], b);
                    mma16816(acc[tm][tn2*2+1], ah[tm], b+2);
                }
            }
        }
    }
    __syncthreads();
    float hv[16], hf[16];
    load_hv16(h_ai, row0, t, hv);
    gate_epilogue(smem, acc, hv, fbi, fbh, t, wm, wn, lane, hf);
    __syncthreads();
    {   // hf -> A tiles
        const int row = t >> 3, j0 = (t & 7)*16;
#pragma unroll
        for (int q = 0; q < 8; q++) {
            __half2 hh = __floats2half2_rn(hf[q*2], hf[q*2+1]);
            *(__half2*)(smem + (uint32_t)row*APITCH + (j0 + q*2)*2) = hh;
        }
    }
    __syncthreads();
    // commit WU ph0 -> X, then WTC chunks0-3 -> SM_W; wait only WU0
    if (t < 128) {
#pragma unroll
        for (int c2 = 0; c2 < 4; c2++) {
            uint32_t dst = sb + SM_X + (uint32_t)c2*8192u + (uint32_t)t*64u;
            const unsigned char* s0 = WU + (size_t)c2*8192 + (size_t)t*64;
#pragma unroll
            for (int q = 0; q < 4; q++) CPA16(dst + q*16, s0 + q*16);
        }
    }
    CPCOMMIT();
    for (uint32_t off = (uint32_t)t*16; off < 147456u; off += 8192u)
        CPA16(sb + SM_W + off, WTC + off);
    CPCOMMIT();
    CPWAIT1();
    __syncthreads();

    // merge ph0 (A=hf) then ph1 (A=h_a)
    float acc2[2][2][4];
#pragma unroll
    for (int a = 0; a < 2; a++)
#pragma unroll
        for (int i = 0; i < 2; i++)
#pragma unroll
            for (int q = 0; q < 4; q++) acc2[a][i][q] = 0.0f;
    for (int ph = 0; ph < 2; ph++) {
        if (ph == 1) {
            load_h_tiles(smem, h_a, row0, t);
            if (t < 128) {
#pragma unroll
                for (int c2 = 0; c2 < 4; c2++) {
                    uint32_t dst = sb + SM_X + (uint32_t)c2*8192u + (uint32_t)t*64u;
                    const unsigned char* s0 = WU + (size_t)(4 + c2)*8192 + (size_t)t*64;
#pragma unroll
                    for (int q = 0; q < 4; q++) CPA16(dst + q*16, s0 + q*16);
                }
            }
            CPCOMMIT(); CPWAIT0();
            __syncthreads();
        }
#pragma unroll
        for (int c2 = 0; c2 < 4; c2++) {
#pragma unroll
            for (int kk = 0; kk < 2; kk++) {
                uint32_t ah[2][4];
#pragma unroll
                for (int tm = 0; tm < 2; tm++)
                    ldsm4(ah[tm], abase + (uint32_t)tm*16u*APITCH + (uint32_t)(c2*32 + kk*16)*2);
                int n = wn*16 + roffB;
                uint32_t ba = sb + SM_X + (uint32_t)c2*8192u + (uint32_t)n*64u
                            + (uint32_t)(((2*kk + sgB + (n>>1)) & 3))*16u;
                uint32_t b[4];
                ldsm4(b, ba);
#pragma unroll
                for (int tm = 0; tm < 2; tm++) {
                    mma16816(acc2[tm][0], ah[tm], b);
                    mma16816(acc2[tm][1], ah[tm], b+2);
                }
            }
        }
        __syncthreads();
    }
    // h2 via exchange at X (WU dead)
    float h2l[16];
    {
        float* exch2 = (float*)(smem + SM_X);
#pragma unroll
        for (int tm = 0; tm < 2; tm++)
#pragma unroll
            for (int tn = 0; tn < 2; tn++) {
                int col = wn*16 + tn*8 + 2*(lane & 3);
                int r1 = wm*32 + tm*16 + (lane >> 2);
                *(float2*)&exch2[r1*132 + col]     = make_float2(acc2[tm][tn][0], acc2[tm][tn][1]);
                *(float2*)&exch2[(r1+8)*132 + col] = make_float2(acc2[tm][tn][2], acc2[tm][tn][3]);
            }
        __syncthreads();
        const int row = t >> 3, j0 = (t & 7)*16;
#pragma unroll
        for (int b = 0; b < 4; b++) {
            int j = j0 + b*4;
            float4 v = *(const float4*)&exch2[row*132 + j];
            float4 b1 = *(const float4*)&ufb[j], b2 = *(const float4*)&uab[j];
            h2l[b*4]   = tanhf(v.x + b1.x + b2.x);
            h2l[b*4+1] = tanhf(v.y + b1.y + b2.y);
            h2l[b*4+2] = tanhf(v.z + b1.z + b2.z);
            h2l[b*4+3] = tanhf(v.w + b1.w + b2.w);
        }
        float* po = h2_out + (size_t)(row0+row)*Hdim + j0;
#pragma unroll
        for (int q = 0; q < 4; q++)
            *(float4*)(po + q*4) = make_float4(h2l[q*4], h2l[q*4+1], h2l[q*4+2], h2l[q*4+3]);
#pragma unroll
        for (int q = 0; q < 8; q++) {
            __half2 hh = __floats2half2_rn(h2l[q*2], h2l[q*2+1]);
            *(__half2*)(smem + (uint32_t)row*APITCH + (j0 + q*2)*2) = hh;
        }
    }
    __syncthreads();
    // chunk4 -> X
    for (int r = t; r < 576; r += 512) {
        uint32_t dst = sb + SM_X + (uint32_t)r*64u;
        const unsigned char* s0 = WTC + 4*36864 + (size_t)r*64;
#pragma unroll
        for (int q = 0; q < 4; q++) CPA16(dst + q*16, s0 + q*16);
    }
    CPCOMMIT();

    // node phase
    float accp[2][4];
#pragma unroll
    for (int a = 0; a < 2; a++) {
#pragma unroll
        for (int i = 0; i < 8; i++)
#pragma unroll
            for (int q = 0; q < 4; q++) acc[a][i][q] = 0.0f;
#pragma unroll
        for (int q = 0; q < 4; q++) accp[a][q] = 0.0f;
    }
    node_gatesA(sb, wm, wn, lane, acc, accp);
    __syncthreads();
    pred_softmax(smem, t, wm, wn, lane, accp, h2o_b, pred_out, probs_out, row0);
    CPWAIT0();
    __syncthreads();
    node_gatesB(sb, wm, wn, lane, acc);
    __syncthreads();

    float hp[16];
    gate_epilogue(smem, acc, h2l, abi, abh, t, wm, wn, lane, hp);
    {
        const int row = t >> 3, j0 = (t & 7)*16;
        float* po = h_out + (size_t)(row0+row)*Hdim + j0;
#pragma unroll
        for (int q = 0; q < 4; q++)
            *(float4*)(po + q*4) = make_float4(hp[q*4], hp[q*4+1], hp[q*4+2], hp[q*4+3]);
    }
}

// ======== host orchestration ========
struct EmitCtx {
    const float *h2o_b, *abi, *abh, *fbi, *fbh, *uab, *ufb;
    const unsigned char *WTC, *WTCF, *WU;
    float *out, *HAI, *H2, *PR;
    int B, idx;
};

static void emit(EmitCtx& P, int lvl, int d, const float* h_in,
                 const float* probsL, const float* haiP, const float* hP) {
    int my = P.idx++;
    float* probs = P.PR  + (size_t)lvl * P.B * Odim;
    float* h_ai  = P.HAI + (size_t)lvl * P.B * Hdim;
    float* pred  = P.out + (size_t)my * P.B * Odim;
    const float* h_self;
    if (probsL) {
        float* h2 = P.H2 + (size_t)lvl * P.B * Hdim;
        fused_tc<<<P.B / 64, 512, SMEM_TC>>>(probsL, haiP, hP,
                                             P.WTCF, P.fbi, P.fbh, P.WU, P.ufb, P.uab,
                                             P.WTC, P.h2o_b, P.abi, P.abh,
                                             h2, pred, probs, h_ai);
        h_self = h2;
    } else {
        node_tc<<<P.B / 64, 512, SMEM_TC>>>(h_in, P.h2o_b, P.WTC, P.abi, P.abh,
                                            pred, probs, h_ai);
        h_self = h_in;
    }
    if (d > 0) {
        emit(P, lvl + 1, d - 1, h_ai, nullptr, nullptr, nullptr);
        emit(P, lvl + 1, d - 1, nullptr,
             P.PR + (size_t)(lvl + 1) * P.B * Odim, h_ai, h_self);
    }
}

extern "C" void kernel_launch(void* const* d_in, const int* in_sizes, int n_in,
                              void* d_out, int out_size) {
    const float* z     = (const float*)d_in[0];
    const float* z2h_w = (const float*)d_in[1];
    const float* z2h_b = (const float*)d_in[2];
    const float* h2o_w = (const float*)d_in[3];
    const float* h2o_b = (const float*)d_in[4];
    const float* awi   = (const float*)d_in[5];
    const float* abi   = (const float*)d_in[6];
    const float* awh   = (const float*)d_in[7];
    const float* abh   = (const float*)d_in[8];
    const float* fwi   = (const float*)d_in[9];
    const float* fbi   = (const float*)d_in[10];
    const float* fwh   = (const float*)d_in[11];
    const float* fbh   = (const float*)d_in[12];
    const float* uaw   = (const float*)d_in[13];
    const float* uab   = (const float*)d_in[14];
    const float* ufw   = (const float*)d_in[15];
    const float* ufb   = (const float*)d_in[16];

    const int H  = in_sizes[2];
    const int O  = in_sizes[4];
    const int IN = in_sizes[1] / H;
    const int B  = in_sizes[0] / IN;
    const int nn = out_size / (B * O);
    int depth = 0;
    while (((2 << depth) - 1) < nn) depth++;

    float *H0p, *HAIp, *H2p, *PRp;
    unsigned char *WTCp, *WTCFp, *WUp;
    cudaGetSymbolAddress((void**)&H0p,  g_H0);
    cudaGetSymbolAddress((void**)&HAIp, g_HAI);
    cudaGetSymbolAddress((void**)&H2p,  g_H2);
    cudaGetSymbolAddress((void**)&PRp,  g_PR);
    cudaGetSymbolAddress((void**)&WTCp, g_WTC);
    cudaGetSymbolAddress((void**)&WTCFp, g_WTCF);
    cudaGetSymbolAddress((void**)&WUp,  g_WU);

    cudaFuncSetAttribute(node_tc,  cudaFuncAttributeMaxDynamicSharedMemorySize, SMEM_TC);
    cudaFuncSetAttribute(fused_tc, cudaFuncAttributeMaxDynamicSharedMemorySize, SMEM_TC);

    pack_wtc<<<(6464 + 127) / 128, 128>>>(awh, awi, fwh, fwi, ufw, uaw, h2o_w, WTCp, WTCFp, WUp);
    init_kernel<<<B / RB, NTHR>>>(z, z2h_w, z2h_b, H0p);

    EmitCtx P;
    P.h2o_b = h2o_b;
    P.abi = abi; P.abh = abh; P.fbi = fbi; P.fbh = fbh;
    P.uab = uab; P.ufb = ufb;
    P.WTC = WTCp; P.WTCF = WTCFp; P.WU = WUp;
    P.out = (float*)d_out;
    P.HAI = HAIp; P.H2 = H2p; P.PR = PRp;
    P.B = B; P.idx = 0;

    emit(P, 0, depth, H0p, nullptr, nullptr, nullptr);
}